// round 3
// baseline (speedup 1.0000x reference)
#include <cuda_runtime.h>

#define NN 50000
#define EE 1600000
#define ETOT 1650000
#define KH 4
#define DHH 64
#define DXX 128
#define CC 256          // KH*DHH
#define NEG 0.01f

// ---------------- scratch (static device globals; allocation-free) ----------
// float4-typed to guarantee 16B alignment for vector loads.
__device__ float4 g_Wx4[NN * 64];        // 51.2 MB  Wx[n][c], c = k*64+d
__device__ float4 g_agg4[NN * 64];       // 51.2 MB
__device__ float4 g_si4[NN];             // si + ab folded in
__device__ float4 g_sj4[NN];
__device__ int g_cnt[NN];
__device__ int g_rowptr[NN + 1];
__device__ int g_cur[NN];
__device__ int g_csr[ETOT];              // src indices grouped by dst
__device__ unsigned g_colmax[CC];
__device__ float g_colsum[CC];

__device__ __forceinline__ unsigned fkey(float f) {
    unsigned b = __float_as_uint(f);
    return (b & 0x80000000u) ? ~b : (b | 0x80000000u);
}
__device__ __forceinline__ float fdec(unsigned u) {
    unsigned b = (u & 0x80000000u) ? (u ^ 0x80000000u) : ~u;
    return __uint_as_float(b);
}
__device__ __forceinline__ int clampi(int v) {
    return v < 0 ? 0 : (v >= NN ? NN - 1 : v);
}

// ---------------- K0: init counters / column reducers ----------------------
__global__ void k_init() {
    int i = blockIdx.x * blockDim.x + threadIdx.x;
    if (i < NN) g_cnt[i] = 0;
    if (i < CC) { g_colmax[i] = 0u; g_colsum[i] = 0.f; }
}

// ---------------- K1: Wx = x @ Ww^T + Wb ------------------------------------
// Block tile: 128 nodes x 128 cols. 256 threads, 8x8 register tile each.
// K=128 processed in 4 chunks of 32 held in static smem (transposed).
__global__ __launch_bounds__(256) void k_wx(const float* __restrict__ x,
                                            const float* __restrict__ Ww,
                                            const float* __restrict__ Wb) {
    __shared__ float XsT[32 * 132];   // [k][node], +4 pad
    __shared__ float WsT[32 * 132];   // [k][col],  +4 pad
    int tid = threadIdx.x;
    int n0 = blockIdx.x * 128;
    int c0 = blockIdx.y * 128;
    int tx = tid & 15, ty = tid >> 4;
    int tx4 = tx * 4, ty4 = ty * 4;

    float acc[8][8];
#pragma unroll
    for (int i = 0; i < 8; i++)
#pragma unroll
        for (int j = 0; j < 8; j++) acc[i][j] = 0.f;

    for (int kc = 0; kc < DXX; kc += 32) {
#pragma unroll
        for (int r = 0; r < 4; r++) {
            int idx = tid + 256 * r;           // 0..1023
            int n = idx >> 3;                  // 0..127
            int k4 = (idx & 7) << 2;           // 0,4,..,28
            int gn = n0 + n; if (gn >= NN) gn = NN - 1;
            float4 v = *(const float4*)&x[(size_t)gn * DXX + kc + k4];
            XsT[(k4 + 0) * 132 + n] = v.x;
            XsT[(k4 + 1) * 132 + n] = v.y;
            XsT[(k4 + 2) * 132 + n] = v.z;
            XsT[(k4 + 3) * 132 + n] = v.w;
            float4 w = *(const float4*)&Ww[(size_t)(c0 + n) * DXX + kc + k4];
            WsT[(k4 + 0) * 132 + n] = w.x;
            WsT[(k4 + 1) * 132 + n] = w.y;
            WsT[(k4 + 2) * 132 + n] = w.z;
            WsT[(k4 + 3) * 132 + n] = w.w;
        }
        __syncthreads();
#pragma unroll 8
        for (int k = 0; k < 32; k++) {
            float4 a0 = *(const float4*)&XsT[k * 132 + ty4];
            float4 a1 = *(const float4*)&XsT[k * 132 + 64 + ty4];
            float4 b0 = *(const float4*)&WsT[k * 132 + tx4];
            float4 b1 = *(const float4*)&WsT[k * 132 + 64 + tx4];
            float av[8] = {a0.x, a0.y, a0.z, a0.w, a1.x, a1.y, a1.z, a1.w};
            float bv[8] = {b0.x, b0.y, b0.z, b0.w, b1.x, b1.y, b1.z, b1.w};
#pragma unroll
            for (int i = 0; i < 8; i++)
#pragma unroll
                for (int j = 0; j < 8; j++) acc[i][j] += av[i] * bv[j];
        }
        __syncthreads();
    }

    float4 bias0 = *(const float4*)&Wb[c0 + tx4];
    float4 bias1 = *(const float4*)&Wb[c0 + 64 + tx4];
#pragma unroll
    for (int i = 0; i < 8; i++) {
        int gn = n0 + ((i < 4) ? (ty4 + i) : (64 + ty4 + i - 4));
        if (gn < NN) {
            float4 o0 = {acc[i][0] + bias0.x, acc[i][1] + bias0.y,
                         acc[i][2] + bias0.z, acc[i][3] + bias0.w};
            float4 o1 = {acc[i][4] + bias1.x, acc[i][5] + bias1.y,
                         acc[i][6] + bias1.z, acc[i][7] + bias1.w};
            g_Wx4[(size_t)gn * 64 + (c0 >> 2) + tx] = o0;
            g_Wx4[(size_t)gn * 64 + (c0 >> 2) + 16 + tx] = o1;
        }
    }
}

// ---------------- K2: si = Wx@a_i + ab, sj = Wx@a_j (warp per node) --------
__global__ __launch_bounds__(256) void k_scores(const float* __restrict__ aw,
                                                const float* __restrict__ ab) {
    int n = (blockIdx.x << 3) + (threadIdx.x >> 5);
    int lane = threadIdx.x & 31;
    if (n >= NN) return;
    const float* row = (const float*)g_Wx4 + (size_t)n * CC;
    float si[KH], sj[KH];
#pragma unroll
    for (int k = 0; k < KH; k++) {
        float va = 0.f, vb = 0.f;
#pragma unroll
        for (int j = 0; j < 2; j++) {
            int d = lane + 32 * j;
            float v = row[k * 64 + d];
            va += v * aw[k * 128 + d];
            vb += v * aw[k * 128 + 64 + d];
        }
#pragma unroll
        for (int o = 16; o; o >>= 1) {
            va += __shfl_xor_sync(0xffffffffu, va, o);
            vb += __shfl_xor_sync(0xffffffffu, vb, o);
        }
        si[k] = va + ab[k];
        sj[k] = vb;
    }
    if (lane == 0) {
        float4 a = {si[0], si[1], si[2], si[3]};
        float4 b = {sj[0], sj[1], sj[2], sj[3]};
        g_si4[n] = a;
        g_sj4[n] = b;
    }
}

// ---------------- K3: degree histogram (edges + self loops) ----------------
// edge_index is INT32 (JAX x64 disabled): 2*EE ints, row 0 = src, row 1 = dst.
__global__ void k_hist(const int* __restrict__ ei) {
    int i = blockIdx.x * blockDim.x + threadIdx.x;
    if (i >= ETOT) return;
    int dst = (i < EE) ? clampi(ei[EE + i]) : (i - EE);
    atomicAdd(&g_cnt[dst], 1);
}

// ---------------- K4: exclusive scan -> rowptr, cur (1 block) --------------
__global__ __launch_bounds__(1024) void k_scan() {
    __shared__ int wsum[32];
    __shared__ int carry_s;
    int tid = threadIdx.x, lane = tid & 31, wid = tid >> 5;
    if (tid == 0) { carry_s = 0; g_rowptr[0] = 0; }
    __syncthreads();
    for (int base = 0; base < NN; base += 1024) {
        int i = base + tid;
        int v = (i < NN) ? g_cnt[i] : 0;
        int s = v;
#pragma unroll
        for (int o = 1; o < 32; o <<= 1) {
            int t = __shfl_up_sync(0xffffffffu, s, o);
            if (lane >= o) s += t;
        }
        if (lane == 31) wsum[wid] = s;
        __syncthreads();
        if (wid == 0) {
            int ws = wsum[lane];
#pragma unroll
            for (int o = 1; o < 32; o <<= 1) {
                int t = __shfl_up_sync(0xffffffffu, ws, o);
                if (lane >= o) ws += t;
            }
            wsum[lane] = ws;
        }
        __syncthreads();
        int wbase = (wid > 0) ? wsum[wid - 1] : 0;
        int incl = carry_s + wbase + s;
        if (i < NN) { g_rowptr[i + 1] = incl; g_cur[i] = incl - v; }
        __syncthreads();
        if (tid == 1023) carry_s = incl;
        __syncthreads();
    }
}

// ---------------- K5: scatter src into CSR ---------------------------------
__global__ void k_scatter(const int* __restrict__ ei) {
    int i = blockIdx.x * blockDim.x + threadIdx.x;
    if (i >= ETOT) return;
    int src, dst;
    if (i < EE) { src = clampi(ei[i]); dst = clampi(ei[EE + i]); }
    else        { src = i - EE;        dst = i - EE; }
    int pos = atomicAdd(&g_cur[dst], 1);
    if (pos < ETOT) g_csr[pos] = src;
}

// ---------------- K6: edge softmax + gather-accumulate (warp/node) ---------
__global__ __launch_bounds__(256) void k_agg() {
    int n = (blockIdx.x << 3) + (threadIdx.x >> 5);
    int lane = threadIdx.x & 31;
    if (n >= NN) return;
    int s = g_rowptr[n], en = g_rowptr[n + 1];
    float4 si4 = g_si4[n];

    // pass 1: denominators. e in ~[-3,3], so exp(e)/sum(exp(e)) needs no
    // max-shift (identical ratio to reference after cancellation).
    float d0 = 0.f, d1 = 0.f, d2 = 0.f, d3 = 0.f;
    for (int e = s + lane; e < en; e += 32) {
        int src = g_csr[e];
        float4 sv = g_sj4[src];
        float t0 = si4.x + sv.x; t0 = t0 < 0.f ? NEG * t0 : t0; d0 += __expf(t0);
        float t1 = si4.y + sv.y; t1 = t1 < 0.f ? NEG * t1 : t1; d1 += __expf(t1);
        float t2 = si4.z + sv.z; t2 = t2 < 0.f ? NEG * t2 : t2; d2 += __expf(t2);
        float t3 = si4.w + sv.w; t3 = t3 < 0.f ? NEG * t3 : t3; d3 += __expf(t3);
    }
#pragma unroll
    for (int o = 16; o; o >>= 1) {
        d0 += __shfl_xor_sync(0xffffffffu, d0, o);
        d1 += __shfl_xor_sync(0xffffffffu, d1, o);
        d2 += __shfl_xor_sync(0xffffffffu, d2, o);
        d3 += __shfl_xor_sync(0xffffffffu, d3, o);
    }
    int ha = lane >> 4;                  // head for low float4: 0/1; high: +2
    float sia = ha ? si4.y : si4.x;
    float sib = ha ? si4.w : si4.z;
    float iva = 1.f / (ha ? d1 : d0);
    float ivb = 1.f / (ha ? d3 : d2);

    float4 a0 = {0.f, 0.f, 0.f, 0.f}, a1 = {0.f, 0.f, 0.f, 0.f};
    for (int e = s; e < en; e++) {
        int src = g_csr[e];
        float4 sv = g_sj4[src];
        float4 w0 = g_Wx4[(size_t)src * 64 + lane];
        float4 w1 = g_Wx4[(size_t)src * 64 + 32 + lane];
        float sja = ha ? sv.y : sv.x;
        float sjb = ha ? sv.w : sv.z;
        float ta = sia + sja; ta = ta < 0.f ? NEG * ta : ta;
        float tb = sib + sjb; tb = tb < 0.f ? NEG * tb : tb;
        float ca = __expf(ta) * iva;
        float cb = __expf(tb) * ivb;
        a0.x += ca * w0.x; a0.y += ca * w0.y; a0.z += ca * w0.z; a0.w += ca * w0.w;
        a1.x += cb * w1.x; a1.y += cb * w1.y; a1.z += cb * w1.z; a1.w += cb * w1.w;
    }
    g_agg4[(size_t)n * 64 + lane] = a0;
    g_agg4[(size_t)n * 64 + 32 + lane] = a1;
}

// ---------------- K7a/K7b: column max / column expsum ----------------------
__global__ __launch_bounds__(256) void k_colmax() {
    const float* A = (const float*)g_agg4;
    int t = threadIdx.x;
    int n0 = blockIdx.x * 200;
    float m = -3.4e38f;
    for (int r = 0; r < 200; r++) m = fmaxf(m, A[(size_t)(n0 + r) * CC + t]);
    atomicMax(&g_colmax[t], fkey(m));
}
__global__ __launch_bounds__(256) void k_colsum() {
    const float* A = (const float*)g_agg4;
    int t = threadIdx.x;
    int n0 = blockIdx.x * 200;
    float mx = fdec(g_colmax[t]);
    float sum = 0.f;
    for (int r = 0; r < 200; r++) sum += __expf(A[(size_t)(n0 + r) * CC + t] - mx);
    atomicAdd(&g_colsum[t], sum);
}

// ---------------- K8: out = softmaxN(agg) @ Wo^T + b (fused GEMM) ----------
// Block: 128 nodes x 64 cols, K=256 in 8 chunks of 32. 8x4 tile per thread.
__global__ __launch_bounds__(256) void k_out(const float* __restrict__ Wo,
                                             const float* __restrict__ Wob,
                                             float* __restrict__ out) {
    __shared__ float EsT[32 * 132];   // [c_local][node]
    __shared__ float WoS[32 * 68];    // [c_local][d]
    __shared__ float smx[CC];
    __shared__ float siv[CC];
    int tid = threadIdx.x;
    int n0 = blockIdx.x * 128;
    int tx = tid & 15, ty = tid >> 4;
    int tx4 = tx * 4, ty4 = ty * 4;
    const float* A = (const float*)g_agg4;

    if (tid < CC) { smx[tid] = fdec(g_colmax[tid]); siv[tid] = 1.f / g_colsum[tid]; }
    __syncthreads();

    float acc[8][4];
#pragma unroll
    for (int i = 0; i < 8; i++)
#pragma unroll
        for (int j = 0; j < 4; j++) acc[i][j] = 0.f;

    for (int cb = 0; cb < CC; cb += 32) {
#pragma unroll
        for (int r = 0; r < 4; r++) {
            int idx = tid + 256 * r;
            int nd = idx >> 3;                 // 0..127
            int c4 = (idx & 7) << 2;           // 0..28
            int gn = n0 + nd; if (gn >= NN) gn = NN - 1;
            float4 v = *(const float4*)&A[(size_t)gn * CC + cb + c4];
            EsT[(c4 + 0) * 132 + nd] = __expf(v.x - smx[cb + c4 + 0]) * siv[cb + c4 + 0];
            EsT[(c4 + 1) * 132 + nd] = __expf(v.y - smx[cb + c4 + 1]) * siv[cb + c4 + 1];
            EsT[(c4 + 2) * 132 + nd] = __expf(v.z - smx[cb + c4 + 2]) * siv[cb + c4 + 2];
            EsT[(c4 + 3) * 132 + nd] = __expf(v.w - smx[cb + c4 + 3]) * siv[cb + c4 + 3];
        }
#pragma unroll
        for (int r = 0; r < 2; r++) {
            int idx = tid + 256 * r;
            int d = idx >> 3;                  // 0..63
            int c4 = (idx & 7) << 2;
            float4 w = *(const float4*)&Wo[(size_t)d * CC + cb + c4];
            WoS[(c4 + 0) * 68 + d] = w.x;
            WoS[(c4 + 1) * 68 + d] = w.y;
            WoS[(c4 + 2) * 68 + d] = w.z;
            WoS[(c4 + 3) * 68 + d] = w.w;
        }
        __syncthreads();
#pragma unroll 8
        for (int k = 0; k < 32; k++) {
            float4 a0 = *(const float4*)&EsT[k * 132 + ty4];
            float4 a1 = *(const float4*)&EsT[k * 132 + 64 + ty4];
            float4 b  = *(const float4*)&WoS[k * 68 + tx4];
            float av[8] = {a0.x, a0.y, a0.z, a0.w, a1.x, a1.y, a1.z, a1.w};
#pragma unroll
            for (int i = 0; i < 8; i++) {
                acc[i][0] += av[i] * b.x;
                acc[i][1] += av[i] * b.y;
                acc[i][2] += av[i] * b.z;
                acc[i][3] += av[i] * b.w;
            }
        }
        __syncthreads();
    }

    float4 bias = *(const float4*)&Wob[tx4];
#pragma unroll
    for (int i = 0; i < 8; i++) {
        int gn = n0 + ((i < 4) ? (ty4 + i) : (64 + ty4 + i - 4));
        if (gn < NN) {
            float4 o = {acc[i][0] + bias.x, acc[i][1] + bias.y,
                        acc[i][2] + bias.z, acc[i][3] + bias.w};
            *(float4*)&out[(size_t)gn * 64 + tx4] = o;
        }
    }
}

// ---------------- launch ----------------------------------------------------
extern "C" void kernel_launch(void* const* d_in, const int* in_sizes, int n_in,
                              void* d_out, int out_size) {
    (void)out_size;
    // Identify inputs by element count (all sizes distinct) — robust to
    // metadata ordering. Fall back to positional order if not found.
    const void* p[8];
    for (int j = 0; j < 8; j++) p[j] = (j < n_in) ? d_in[j] : 0;
    const int want[8] = {2 * EE,          // edge_index (int32)
                         NN * DXX,        // x
                         KH * DHH * DXX,  // Ww
                         KH * DHH,        // Wb
                         KH * 2 * DHH,    // aw
                         KH,              // ab
                         DHH * CC,        // Wo_w
                         DHH};            // Wo_b
    for (int j = 0; j < 8; j++)
        for (int i = 0; i < n_in; i++)
            if (in_sizes[i] == want[j]) { p[j] = d_in[i]; break; }

    const int*   ei  = (const int*)p[0];
    const float* x   = (const float*)p[1];
    const float* Ww  = (const float*)p[2];
    const float* Wb  = (const float*)p[3];
    const float* aw  = (const float*)p[4];
    const float* ab  = (const float*)p[5];
    const float* Wo  = (const float*)p[6];
    const float* Wob = (const float*)p[7];
    float* out = (float*)d_out;

    k_init<<<196, 256>>>();
    dim3 gwx(391, 2);
    k_wx<<<gwx, 256>>>(x, Ww, Wb);
    k_scores<<<(NN + 7) / 8, 256>>>(aw, ab);
    k_hist<<<(ETOT + 255) / 256, 256>>>(ei);
    k_scan<<<1, 1024>>>();
    k_scatter<<<(ETOT + 255) / 256, 256>>>(ei);
    k_agg<<<(NN + 7) / 8, 256>>>();
    k_colmax<<<250, 256>>>();
    k_colsum<<<250, 256>>>();
    k_out<<<391, 256>>>(Wo, Wob, out);
}

// round 4
// speedup vs baseline: 1.0605x; 1.0605x over previous
#include <cuda_runtime.h>
#include <cuda_bf16.h>

typedef unsigned long long ull;

#define NN 50000
#define EE 1600000
#define ETOT 1650000
#define KH 4
#define DHH 64
#define DXX 128
#define CC 256          // KH*DHH
#define NEG 0.01f

// ---------------- scratch (static device globals; allocation-free) ----------
__device__ uint4 g_Wxh4[NN * 32];        // 25.6 MB  bf16 Wx[n][c] (512B/row)
__device__ uint4 g_aggh4[NN * 32];       // 25.6 MB  bf16 agg
__device__ float4 g_si4[NN];             // si + ab folded in (per head)
__device__ float4 g_sj4[NN];
__device__ int g_cnt[NN];
__device__ int g_rowptr[NN + 1];
__device__ int g_cur[NN];
__device__ int g_csr[ETOT];              // src indices grouped by dst
__device__ float g_colsum[CC];

// ---------------- helpers ---------------------------------------------------
__device__ __forceinline__ float bflo(unsigned u) { return __uint_as_float(u << 16); }
__device__ __forceinline__ float bfhi(unsigned u) { return __uint_as_float(u & 0xffff0000u); }
__device__ __forceinline__ int clampi(int v) {
    return v < 0 ? 0 : (v >= NN ? NN - 1 : v);
}

#define PACK_DUP(d, f) asm("mov.b64 %0, {%1, %1};" : "=l"(d) : "f"(f))
#define FMA2(d, a, b) asm("fma.rn.f32x2 %0, %1, %2, %0;" : "+l"(d) : "l"(a), "l"(b))
#define UNPACK2(lo, hi, d) asm("mov.b64 {%0, %1}, %2;" : "=f"(lo), "=f"(hi) : "l"(d))
// result: low 16 bits = bf16(lo), high 16 bits = bf16(hi)
#define PACKBF(r, lo, hi) asm("cvt.rn.bf16x2.f32 %0, %1, %2;" : "=r"(r) : "f"(hi), "f"(lo))

// ---------------- K0: init --------------------------------------------------
__global__ void k_init() {
    int i = blockIdx.x * blockDim.x + threadIdx.x;
    if (i < NN) g_cnt[i] = 0;
    if (i < CC) g_colsum[i] = 0.f;
}

// ---------------- K1: Wx = x @ Ww^T + Wb  (bf16 out, f32x2 math) ------------
// Block tile: 128 nodes x 128 cols. 256 threads, 8x8 register tile (4 f32x2
// accumulator pairs along the col axis).
__global__ __launch_bounds__(256) void k_wx(const float* __restrict__ x,
                                            const float* __restrict__ Ww,
                                            const float* __restrict__ Wb) {
    __shared__ __align__(16) float XsT[32 * 132];   // [k][node]
    __shared__ __align__(16) float WsT[32 * 132];   // [k][col]
    int tid = threadIdx.x;
    int n0 = blockIdx.x * 128;
    int c0 = blockIdx.y * 128;
    int tx = tid & 15, ty = tid >> 4;
    int tx4 = tx * 4, ty4 = ty * 4;

    ull acc2[8][4];
#pragma unroll
    for (int i = 0; i < 8; i++)
#pragma unroll
        for (int j = 0; j < 4; j++) acc2[i][j] = 0ull;

    for (int kc = 0; kc < DXX; kc += 32) {
#pragma unroll
        for (int r = 0; r < 4; r++) {
            int idx = tid + 256 * r;           // 0..1023
            int n = idx >> 3;                  // 0..127
            int k4 = (idx & 7) << 2;           // 0,4,..,28
            int gn = n0 + n; if (gn >= NN) gn = NN - 1;
            float4 v = *(const float4*)&x[(size_t)gn * DXX + kc + k4];
            XsT[(k4 + 0) * 132 + n] = v.x;
            XsT[(k4 + 1) * 132 + n] = v.y;
            XsT[(k4 + 2) * 132 + n] = v.z;
            XsT[(k4 + 3) * 132 + n] = v.w;
            float4 w = *(const float4*)&Ww[(size_t)(c0 + n) * DXX + kc + k4];
            WsT[(k4 + 0) * 132 + n] = w.x;
            WsT[(k4 + 1) * 132 + n] = w.y;
            WsT[(k4 + 2) * 132 + n] = w.z;
            WsT[(k4 + 3) * 132 + n] = w.w;
        }
        __syncthreads();
#pragma unroll 8
        for (int k = 0; k < 32; k++) {
            float4 a0 = *(const float4*)&XsT[k * 132 + ty4];
            float4 a1 = *(const float4*)&XsT[k * 132 + 64 + ty4];
            ulonglong2 bp0 = *(const ulonglong2*)&WsT[k * 132 + tx4];
            ulonglong2 bp1 = *(const ulonglong2*)&WsT[k * 132 + 64 + tx4];
            float av[8] = {a0.x, a0.y, a0.z, a0.w, a1.x, a1.y, a1.z, a1.w};
#pragma unroll
            for (int i = 0; i < 8; i++) {
                ull ad; PACK_DUP(ad, av[i]);
                FMA2(acc2[i][0], ad, bp0.x);
                FMA2(acc2[i][1], ad, bp0.y);
                FMA2(acc2[i][2], ad, bp1.x);
                FMA2(acc2[i][3], ad, bp1.y);
            }
        }
        __syncthreads();
    }

    float b[8];
#pragma unroll
    for (int j = 0; j < 4; j++) { b[j] = Wb[c0 + tx4 + j]; b[4 + j] = Wb[c0 + 64 + tx4 + j]; }
    unsigned short* Wh = (unsigned short*)g_Wxh4;
#pragma unroll
    for (int i = 0; i < 8; i++) {
        int gn = n0 + ((i < 4) ? (ty4 + i) : (64 + ty4 + i - 4));
        if (gn < NN) {
            float v[8];
#pragma unroll
            for (int j = 0; j < 4; j++) UNPACK2(v[2 * j], v[2 * j + 1], acc2[i][j]);
            unsigned p0, p1, p2, p3;
            PACKBF(p0, v[0] + b[0], v[1] + b[1]);
            PACKBF(p1, v[2] + b[2], v[3] + b[3]);
            PACKBF(p2, v[4] + b[4], v[5] + b[5]);
            PACKBF(p3, v[6] + b[6], v[7] + b[7]);
            *(uint2*)&Wh[(size_t)gn * 256 + c0 + tx4] = make_uint2(p0, p1);
            *(uint2*)&Wh[(size_t)gn * 256 + c0 + 64 + tx4] = make_uint2(p2, p3);
        }
    }
}

// ---------------- K2: si/sj scores from bf16 Wx (warp per node) ------------
__global__ __launch_bounds__(256) void k_scores(const float* __restrict__ aw,
                                                const float* __restrict__ ab) {
    int n = (blockIdx.x << 3) + (threadIdx.x >> 5);
    int lane = threadIdx.x & 31;
    if (n >= NN) return;
    int h = lane >> 3;                 // head
    int dd = (lane & 7) * 8;           // within-head col base
    uint4 u = g_Wxh4[(size_t)n * 32 + lane];
    float f[8] = {bflo(u.x), bfhi(u.x), bflo(u.y), bfhi(u.y),
                  bflo(u.z), bfhi(u.z), bflo(u.w), bfhi(u.w)};
    const float* ai = aw + h * 128 + dd;
    const float* aj = ai + 64;
    float va = 0.f, vb = 0.f;
#pragma unroll
    for (int j = 0; j < 8; j++) { va += f[j] * ai[j]; vb += f[j] * aj[j]; }
#pragma unroll
    for (int o = 4; o; o >>= 1) {
        va += __shfl_xor_sync(0xffffffffu, va, o);
        vb += __shfl_xor_sync(0xffffffffu, vb, o);
    }
    if ((lane & 7) == 0) {
        ((float*)g_si4)[n * 4 + h] = va + ab[h];
        ((float*)g_sj4)[n * 4 + h] = vb;
    }
}

// ---------------- K3: degree histogram (edges + self loops) ----------------
__global__ void k_hist(const int* __restrict__ ei) {
    int i = blockIdx.x * blockDim.x + threadIdx.x;
    if (i >= ETOT) return;
    int dst = (i < EE) ? clampi(ei[EE + i]) : (i - EE);
    atomicAdd(&g_cnt[dst], 1);
}

// ---------------- K4: exclusive scan -> rowptr, cur (1 block) --------------
__global__ __launch_bounds__(1024) void k_scan() {
    __shared__ int wsum[32];
    __shared__ int carry_s;
    int tid = threadIdx.x, lane = tid & 31, wid = tid >> 5;
    if (tid == 0) { carry_s = 0; g_rowptr[0] = 0; }
    __syncthreads();
    for (int base = 0; base < NN; base += 1024) {
        int i = base + tid;
        int v = (i < NN) ? g_cnt[i] : 0;
        int s = v;
#pragma unroll
        for (int o = 1; o < 32; o <<= 1) {
            int t = __shfl_up_sync(0xffffffffu, s, o);
            if (lane >= o) s += t;
        }
        if (lane == 31) wsum[wid] = s;
        __syncthreads();
        if (wid == 0) {
            int ws = wsum[lane];
#pragma unroll
            for (int o = 1; o < 32; o <<= 1) {
                int t = __shfl_up_sync(0xffffffffu, ws, o);
                if (lane >= o) ws += t;
            }
            wsum[lane] = ws;
        }
        __syncthreads();
        int wbase = (wid > 0) ? wsum[wid - 1] : 0;
        int incl = carry_s + wbase + s;
        if (i < NN) { g_rowptr[i + 1] = incl; g_cur[i] = incl - v; }
        __syncthreads();
        if (tid == 1023) carry_s = incl;
        __syncthreads();
    }
}

// ---------------- K5: scatter src into CSR ---------------------------------
__global__ void k_scatter(const int* __restrict__ ei) {
    int i = blockIdx.x * blockDim.x + threadIdx.x;
    if (i >= ETOT) return;
    int src, dst;
    if (i < EE) { src = clampi(ei[i]); dst = clampi(ei[EE + i]); }
    else        { src = i - EE;        dst = i - EE; }
    int pos = atomicAdd(&g_cur[dst], 1);
    if (pos < ETOT) g_csr[pos] = src;
}

// ---------------- K6: single-pass edge softmax + gather (warp/node) --------
// acc = sum exp(e)*Wx[src]; den = sum exp(e); agg = acc/den (ratio identical
// to reference's max-shifted softmax). Payload gathered in bf16 (512B/edge).
__global__ __launch_bounds__(256) void k_agg() {
    int n = (blockIdx.x << 3) + (threadIdx.x >> 5);
    int lane = threadIdx.x & 31;
    if (n >= NN) return;
    int h = lane >> 3;
    int s = g_rowptr[n], en = g_rowptr[n + 1];
    float4 siv = g_si4[n];
    float si = (h < 2) ? (h ? siv.y : siv.x) : ((h == 3) ? siv.w : siv.z);

    float a0 = 0.f, a1 = 0.f, a2 = 0.f, a3 = 0.f;
    float a4 = 0.f, a5 = 0.f, a6 = 0.f, a7 = 0.f;
    float den = 0.f;

    // software pipeline depth 2 (deg >= 1 guaranteed by self-loops)
    int src0 = g_csr[s];
    float4 sj0 = g_sj4[src0];
    uint4 u0 = g_Wxh4[(size_t)src0 * 32 + lane];
    for (int e = s; e < en; e++) {
        float4 sjn = sj0; uint4 un = u0;
        if (e + 1 < en) {
            int src1 = g_csr[e + 1];
            sjn = g_sj4[src1];
            un = g_Wxh4[(size_t)src1 * 32 + lane];
        }
        float sj = (h < 2) ? (h ? sj0.y : sj0.x) : ((h == 3) ? sj0.w : sj0.z);
        float t = si + sj; t = t < 0.f ? NEG * t : t;
        float c = __expf(t);
        den += c;
        a0 += c * bflo(u0.x); a1 += c * bfhi(u0.x);
        a2 += c * bflo(u0.y); a3 += c * bfhi(u0.y);
        a4 += c * bflo(u0.z); a5 += c * bfhi(u0.z);
        a6 += c * bflo(u0.w); a7 += c * bfhi(u0.w);
        sj0 = sjn; u0 = un;
    }
    float inv = 1.f / den;
    unsigned p0, p1, p2, p3;
    PACKBF(p0, a0 * inv, a1 * inv);
    PACKBF(p1, a2 * inv, a3 * inv);
    PACKBF(p2, a4 * inv, a5 * inv);
    PACKBF(p3, a6 * inv, a7 * inv);
    g_aggh4[(size_t)n * 32 + lane] = make_uint4(p0, p1, p2, p3);
}

// ---------------- K7: column exp-sum (no max-shift needed) -----------------
__global__ __launch_bounds__(256) void k_colsum() {
    const unsigned* Ah = (const unsigned*)g_aggh4;
    int tid = threadIdx.x;
    int c2 = tid & 127;                // uint index = column pair
    int g = tid >> 7;
    int n0 = blockIdx.x * 200;
    float s0 = 0.f, s1 = 0.f;
    for (int r = g; r < 200; r += 2) {
        unsigned u = Ah[(size_t)(n0 + r) * 128 + c2];
        s0 += __expf(bflo(u));
        s1 += __expf(bfhi(u));
    }
    atomicAdd(&g_colsum[c2 * 2], s0);
    atomicAdd(&g_colsum[c2 * 2 + 1], s1);
}

// ---------------- K8: out = softmaxN(agg) @ Wo^T + b (fused GEMM) ----------
__global__ __launch_bounds__(256) void k_out(const float* __restrict__ Wo,
                                             const float* __restrict__ Wob,
                                             float* __restrict__ out) {
    __shared__ __align__(16) float EsT[32 * 132];   // [c_local][node]
    __shared__ __align__(16) float WoS[32 * 68];    // [c_local][d]
    __shared__ float siv[CC];
    int tid = threadIdx.x;
    int n0 = blockIdx.x * 128;
    int tx = tid & 15, ty = tid >> 4;
    int tx4 = tx * 4, ty4 = ty * 4;
    const unsigned short* Ah = (const unsigned short*)g_aggh4;

    if (tid < CC) siv[tid] = 1.f / g_colsum[tid];
    __syncthreads();

    float acc[8][4];
#pragma unroll
    for (int i = 0; i < 8; i++)
#pragma unroll
        for (int j = 0; j < 4; j++) acc[i][j] = 0.f;

    for (int cb = 0; cb < CC; cb += 32) {
#pragma unroll
        for (int r = 0; r < 4; r++) {
            int idx = tid + 256 * r;
            int nd = idx >> 3;                 // 0..127
            int c4 = (idx & 7) << 2;           // 0..28
            int gn = n0 + nd; if (gn >= NN) gn = NN - 1;
            uint2 u = *(const uint2*)&Ah[(size_t)gn * 256 + cb + c4];
            EsT[(c4 + 0) * 132 + nd] = __expf(bflo(u.x)) * siv[cb + c4 + 0];
            EsT[(c4 + 1) * 132 + nd] = __expf(bfhi(u.x)) * siv[cb + c4 + 1];
            EsT[(c4 + 2) * 132 + nd] = __expf(bflo(u.y)) * siv[cb + c4 + 2];
            EsT[(c4 + 3) * 132 + nd] = __expf(bfhi(u.y)) * siv[cb + c4 + 3];
        }
#pragma unroll
        for (int r = 0; r < 2; r++) {
            int idx = tid + 256 * r;
            int d = idx >> 3;                  // 0..63
            int c4 = (idx & 7) << 2;
            float4 w = *(const float4*)&Wo[(size_t)d * CC + cb + c4];
            WoS[(c4 + 0) * 68 + d] = w.x;
            WoS[(c4 + 1) * 68 + d] = w.y;
            WoS[(c4 + 2) * 68 + d] = w.z;
            WoS[(c4 + 3) * 68 + d] = w.w;
        }
        __syncthreads();
#pragma unroll 8
        for (int k = 0; k < 32; k++) {
            float4 a0 = *(const float4*)&EsT[k * 132 + ty4];
            float4 a1 = *(const float4*)&EsT[k * 132 + 64 + ty4];
            float4 bv = *(const float4*)&WoS[k * 68 + tx4];
            float av[8] = {a0.x, a0.y, a0.z, a0.w, a1.x, a1.y, a1.z, a1.w};
#pragma unroll
            for (int i = 0; i < 8; i++) {
                acc[i][0] += av[i] * bv.x;
                acc[i][1] += av[i] * bv.y;
                acc[i][2] += av[i] * bv.z;
                acc[i][3] += av[i] * bv.w;
            }
        }
        __syncthreads();
    }

    float4 bias = *(const float4*)&Wob[tx4];
#pragma unroll
    for (int i = 0; i < 8; i++) {
        int gn = n0 + ((i < 4) ? (ty4 + i) : (64 + ty4 + i - 4));
        if (gn < NN) {
            float4 o = {acc[i][0] + bias.x, acc[i][1] + bias.y,
                        acc[i][2] + bias.z, acc[i][3] + bias.w};
            *(float4*)&out[(size_t)gn * 64 + tx4] = o;
        }
    }
}

// ---------------- launch ----------------------------------------------------
extern "C" void kernel_launch(void* const* d_in, const int* in_sizes, int n_in,
                              void* d_out, int out_size) {
    (void)out_size;
    const void* p[8];
    for (int j = 0; j < 8; j++) p[j] = (j < n_in) ? d_in[j] : 0;
    const int want[8] = {2 * EE, NN * DXX, KH * DHH * DXX, KH * DHH,
                         KH * 2 * DHH, KH, DHH * CC, DHH};
    for (int j = 0; j < 8; j++)
        for (int i = 0; i < n_in; i++)
            if (in_sizes[i] == want[j]) { p[j] = d_in[i]; break; }

    const int*   ei  = (const int*)p[0];
    const float* x   = (const float*)p[1];
    const float* Ww  = (const float*)p[2];
    const float* Wb  = (const float*)p[3];
    const float* aw  = (const float*)p[4];
    const float* ab  = (const float*)p[5];
    const float* Wo  = (const float*)p[6];
    const float* Wob = (const float*)p[7];
    float* out = (float*)d_out;

    k_init<<<196, 256>>>();
    dim3 gwx(391, 2);
    k_wx<<<gwx, 256>>>(x, Ww, Wb);
    k_scores<<<(NN + 7) / 8, 256>>>(aw, ab);
    k_hist<<<(ETOT + 255) / 256, 256>>>(ei);
    k_scan<<<1, 1024>>>();
    k_scatter<<<(ETOT + 255) / 256, 256>>>(ei);
    k_agg<<<(NN + 7) / 8, 256>>>();
    k_colsum<<<250, 256>>>();
    k_out<<<391, 256>>>(Wo, Wob, out);
}

// round 5
// speedup vs baseline: 1.1603x; 1.0941x over previous
#include <cuda_runtime.h>
#include <cuda_bf16.h>

typedef unsigned long long ull;

#define NN 50000
#define EE 1600000
#define ETOT 1650000
#define KH 4
#define DHH 64
#define DXX 128
#define CC 256          // KH*DHH
#define NEG 0.01f
#define SCB 49          // scan blocks (49*1024 >= NN)

// ---------------- scratch (static device globals; allocation-free) ----------
__device__ uint4 g_Wxh4[NN * 32];        // 25.6 MB  bf16 Wx[n][c] (512B/row)
__device__ uint4 g_aggh4[NN * 32];       // 25.6 MB  bf16 agg
__device__ float4 g_si4[NN];             // si + ab folded in (per head)
__device__ float4 g_sj4[NN];
__device__ int g_cnt[NN];
__device__ int g_rowptr[NN + 1];
__device__ int g_cur[NN];
__device__ int g_bsum[64];
__device__ int g_csr[ETOT];              // src indices grouped by dst
__device__ float g_colsum[CC];

// ---------------- helpers ---------------------------------------------------
__device__ __forceinline__ float bflo(unsigned u) { return __uint_as_float(u << 16); }
__device__ __forceinline__ float bfhi(unsigned u) { return __uint_as_float(u & 0xffff0000u); }
__device__ __forceinline__ int clampi(int v) {
    return v < 0 ? 0 : (v >= NN ? NN - 1 : v);
}

#define PACK_DUP(d, f) asm("mov.b64 %0, {%1, %1};" : "=l"(d) : "f"(f))
#define FMA2(d, a, b) asm("fma.rn.f32x2 %0, %1, %2, %0;" : "+l"(d) : "l"(a), "l"(b))
#define UNPACK2(lo, hi, d) asm("mov.b64 {%0, %1}, %2;" : "=f"(lo), "=f"(hi) : "l"(d))
// result: low 16 bits = bf16(lo), high 16 bits = bf16(hi)
#define PACKBF(r, lo, hi) asm("cvt.rn.bf16x2.f32 %0, %1, %2;" : "=r"(r) : "f"(hi), "f"(lo))

// ---------------- K0: init (cnt=1 accounts for the self loop) ---------------
__global__ void k_init() {
    int i = blockIdx.x * blockDim.x + threadIdx.x;
    if (i < NN) g_cnt[i] = 1;
    if (i < CC) g_colsum[i] = 0.f;
}

// ---------------- K1: Wx = x @ Ww^T + Wb  (bf16 out, f32x2 math) ------------
__global__ __launch_bounds__(256) void k_wx(const float* __restrict__ x,
                                            const float* __restrict__ Ww,
                                            const float* __restrict__ Wb) {
    __shared__ __align__(16) float XsT[32 * 132];   // [k][node]
    __shared__ __align__(16) float WsT[32 * 132];   // [k][col]
    int tid = threadIdx.x;
    int n0 = blockIdx.x * 128;
    int c0 = blockIdx.y * 128;
    int tx = tid & 15, ty = tid >> 4;
    int tx4 = tx * 4, ty4 = ty * 4;

    ull acc2[8][4];
#pragma unroll
    for (int i = 0; i < 8; i++)
#pragma unroll
        for (int j = 0; j < 4; j++) acc2[i][j] = 0ull;

    for (int kc = 0; kc < DXX; kc += 32) {
#pragma unroll
        for (int r = 0; r < 4; r++) {
            int idx = tid + 256 * r;           // 0..1023
            int n = idx >> 3;                  // 0..127
            int k4 = (idx & 7) << 2;           // 0,4,..,28
            int gn = n0 + n; if (gn >= NN) gn = NN - 1;
            float4 v = *(const float4*)&x[(size_t)gn * DXX + kc + k4];
            XsT[(k4 + 0) * 132 + n] = v.x;
            XsT[(k4 + 1) * 132 + n] = v.y;
            XsT[(k4 + 2) * 132 + n] = v.z;
            XsT[(k4 + 3) * 132 + n] = v.w;
            float4 w = *(const float4*)&Ww[(size_t)(c0 + n) * DXX + kc + k4];
            WsT[(k4 + 0) * 132 + n] = w.x;
            WsT[(k4 + 1) * 132 + n] = w.y;
            WsT[(k4 + 2) * 132 + n] = w.z;
            WsT[(k4 + 3) * 132 + n] = w.w;
        }
        __syncthreads();
#pragma unroll 8
        for (int k = 0; k < 32; k++) {
            float4 a0 = *(const float4*)&XsT[k * 132 + ty4];
            float4 a1 = *(const float4*)&XsT[k * 132 + 64 + ty4];
            ulonglong2 bp0 = *(const ulonglong2*)&WsT[k * 132 + tx4];
            ulonglong2 bp1 = *(const ulonglong2*)&WsT[k * 132 + 64 + tx4];
            float av[8] = {a0.x, a0.y, a0.z, a0.w, a1.x, a1.y, a1.z, a1.w};
#pragma unroll
            for (int i = 0; i < 8; i++) {
                ull ad; PACK_DUP(ad, av[i]);
                FMA2(acc2[i][0], ad, bp0.x);
                FMA2(acc2[i][1], ad, bp0.y);
                FMA2(acc2[i][2], ad, bp1.x);
                FMA2(acc2[i][3], ad, bp1.y);
            }
        }
        __syncthreads();
    }

    float b[8];
#pragma unroll
    for (int j = 0; j < 4; j++) { b[j] = Wb[c0 + tx4 + j]; b[4 + j] = Wb[c0 + 64 + tx4 + j]; }
    unsigned short* Wh = (unsigned short*)g_Wxh4;
#pragma unroll
    for (int i = 0; i < 8; i++) {
        int gn = n0 + ((i < 4) ? (ty4 + i) : (64 + ty4 + i - 4));
        if (gn < NN) {
            float v[8];
#pragma unroll
            for (int j = 0; j < 4; j++) UNPACK2(v[2 * j], v[2 * j + 1], acc2[i][j]);
            unsigned p0, p1, p2, p3;
            PACKBF(p0, v[0] + b[0], v[1] + b[1]);
            PACKBF(p1, v[2] + b[2], v[3] + b[3]);
            PACKBF(p2, v[4] + b[4], v[5] + b[5]);
            PACKBF(p3, v[6] + b[6], v[7] + b[7]);
            *(uint2*)&Wh[(size_t)gn * 256 + c0 + tx4] = make_uint2(p0, p1);
            *(uint2*)&Wh[(size_t)gn * 256 + c0 + 64 + tx4] = make_uint2(p2, p3);
        }
    }
}

// ---------------- K2: si/sj scores from bf16 Wx (8 lanes per head) ---------
__global__ __launch_bounds__(256) void k_scores(const float* __restrict__ aw,
                                                const float* __restrict__ ab) {
    int n = (blockIdx.x << 3) + (threadIdx.x >> 5);
    int lane = threadIdx.x & 31;
    if (n >= NN) return;
    int h = lane >> 3;                 // head
    int dd = (lane & 7) * 8;           // within-head col base
    uint4 u = g_Wxh4[(size_t)n * 32 + lane];
    float f[8] = {bflo(u.x), bfhi(u.x), bflo(u.y), bfhi(u.y),
                  bflo(u.z), bfhi(u.z), bflo(u.w), bfhi(u.w)};
    const float* ai = aw + h * 128 + dd;
    const float* aj = ai + 64;
    float va = 0.f, vb = 0.f;
#pragma unroll
    for (int j = 0; j < 8; j++) { va += f[j] * ai[j]; vb += f[j] * aj[j]; }
#pragma unroll
    for (int o = 4; o; o >>= 1) {
        va += __shfl_xor_sync(0xffffffffu, va, o);
        vb += __shfl_xor_sync(0xffffffffu, vb, o);
    }
    if ((lane & 7) == 0) {
        ((float*)g_si4)[n * 4 + h] = va + ab[h];
        ((float*)g_sj4)[n * 4 + h] = vb;
    }
}

// ---------------- K3: degree histogram, 2 edges/thread ----------------------
__global__ void k_hist(const int* __restrict__ ei) {
    int i = blockIdx.x * blockDim.x + threadIdx.x;
    if (i >= EE / 2) return;
    int2 d2 = *(const int2*)&ei[EE + 2 * i];
    atomicAdd(&g_cnt[clampi(d2.x)], 1);
    atomicAdd(&g_cnt[clampi(d2.y)], 1);
}

// ---------------- K4abc: parallel exclusive scan ---------------------------
__global__ __launch_bounds__(1024) void k_scan1() {
    __shared__ int wsum[32];
    int tid = threadIdx.x, lane = tid & 31, wid = tid >> 5;
    int i = blockIdx.x * 1024 + tid;
    int v = (i < NN) ? g_cnt[i] : 0;
    int s = v;
#pragma unroll
    for (int o = 1; o < 32; o <<= 1) {
        int t = __shfl_up_sync(0xffffffffu, s, o);
        if (lane >= o) s += t;
    }
    if (lane == 31) wsum[wid] = s;
    __syncthreads();
    if (wid == 0) {
        int ws = wsum[lane];
#pragma unroll
        for (int o = 1; o < 32; o <<= 1) {
            int t = __shfl_up_sync(0xffffffffu, ws, o);
            if (lane >= o) ws += t;
        }
        wsum[lane] = ws;
    }
    __syncthreads();
    int incl = s + (wid > 0 ? wsum[wid - 1] : 0);
    if (i < NN) { g_rowptr[i + 1] = incl; g_cur[i] = incl - v; }
    if (tid == 1023) g_bsum[blockIdx.x] = incl;
}
__global__ void k_scan2() {       // 64 threads, scan SCB block totals
    int tid = threadIdx.x, lane = tid & 31, wid = tid >> 5;
    __shared__ int w0;
    int v = (tid < SCB) ? g_bsum[tid] : 0;
    int s = v;
#pragma unroll
    for (int o = 1; o < 32; o <<= 1) {
        int t = __shfl_up_sync(0xffffffffu, s, o);
        if (lane >= o) s += t;
    }
    if (tid == 31) w0 = s;
    __syncthreads();
    if (wid == 1) s += w0;
    if (tid < SCB) g_bsum[tid] = s - v;   // exclusive
}
__global__ __launch_bounds__(1024) void k_scan3() {
    int off = g_bsum[blockIdx.x];
    int i = blockIdx.x * 1024 + threadIdx.x;
    if (i < NN) { g_rowptr[i + 1] += off; g_cur[i] += off; }
    if (i == 0) g_rowptr[0] = 0;
}

// ---------------- K5: scatter src into CSR (2 edges/thread + loops) --------
__global__ void k_scatter(const int* __restrict__ ei) {
    int i = blockIdx.x * blockDim.x + threadIdx.x;
    if (i < EE / 2) {
        int2 s2 = *(const int2*)&ei[2 * i];
        int2 d2 = *(const int2*)&ei[EE + 2 * i];
        int pa = atomicAdd(&g_cur[clampi(d2.x)], 1);
        int pb = atomicAdd(&g_cur[clampi(d2.y)], 1);
        if (pa < ETOT) g_csr[pa] = clampi(s2.x);
        if (pb < ETOT) g_csr[pb] = clampi(s2.y);
    } else {
        int n = i - EE / 2;
        if (n < NN) {
            int pos = atomicAdd(&g_cur[n], 1);
            if (pos < ETOT) g_csr[pos] = n;
        }
    }
}

// ---------------- K6: single-pass edge softmax + gather, depth-4 pipe ------
__global__ __launch_bounds__(256) void k_agg() {
    int n = (blockIdx.x << 3) + (threadIdx.x >> 5);
    int lane = threadIdx.x & 31;
    if (n >= NN) return;
    int h = lane >> 3;
    int s = g_rowptr[n], en = g_rowptr[n + 1];
    float4 siv = g_si4[n];
    float si = (h < 2) ? (h ? siv.y : siv.x) : ((h == 3) ? siv.w : siv.z);

    float a0 = 0.f, a1 = 0.f, a2 = 0.f, a3 = 0.f;
    float a4 = 0.f, a5 = 0.f, a6 = 0.f, a7 = 0.f;
    float den = 0.f;

    int srcA = g_csr[s];
    int srcB = (s + 1 < en) ? g_csr[s + 1] : srcA;
    float4 sjA = g_sj4[srcA], sjB = g_sj4[srcB];
    uint4 uA = g_Wxh4[(size_t)srcA * 32 + lane];
    uint4 uB = g_Wxh4[(size_t)srcB * 32 + lane];

    for (int e = s; e < en; e += 2) {
        int nA = (e + 2 < en) ? g_csr[e + 2] : srcA;
        int nB = (e + 3 < en) ? g_csr[e + 3] : srcA;
        float4 sjAn = g_sj4[nA];
        uint4 uAn = g_Wxh4[(size_t)nA * 32 + lane];
        float4 sjBn = g_sj4[nB];
        uint4 uBn = g_Wxh4[(size_t)nB * 32 + lane];

        float sj = (h < 2) ? (h ? sjA.y : sjA.x) : ((h == 3) ? sjA.w : sjA.z);
        float t = si + sj; t = t < 0.f ? NEG * t : t;
        float c = __expf(t);
        den += c;
        a0 += c * bflo(uA.x); a1 += c * bfhi(uA.x);
        a2 += c * bflo(uA.y); a3 += c * bfhi(uA.y);
        a4 += c * bflo(uA.z); a5 += c * bfhi(uA.z);
        a6 += c * bflo(uA.w); a7 += c * bfhi(uA.w);

        if (e + 1 < en) {
            float sjb = (h < 2) ? (h ? sjB.y : sjB.x) : ((h == 3) ? sjB.w : sjB.z);
            float tb = si + sjb; tb = tb < 0.f ? NEG * tb : tb;
            float cb = __expf(tb);
            den += cb;
            a0 += cb * bflo(uB.x); a1 += cb * bfhi(uB.x);
            a2 += cb * bflo(uB.y); a3 += cb * bfhi(uB.y);
            a4 += cb * bflo(uB.z); a5 += cb * bfhi(uB.z);
            a6 += cb * bflo(uB.w); a7 += cb * bfhi(uB.w);
        }
        sjA = sjAn; uA = uAn; sjB = sjBn; uB = uBn;
    }
    float inv = 1.f / den;
    unsigned p0, p1, p2, p3;
    PACKBF(p0, a0 * inv, a1 * inv);
    PACKBF(p1, a2 * inv, a3 * inv);
    PACKBF(p2, a4 * inv, a5 * inv);
    PACKBF(p3, a6 * inv, a7 * inv);
    g_aggh4[(size_t)n * 32 + lane] = make_uint4(p0, p1, p2, p3);
}

// ---------------- K7: column exp-sum (no max-shift needed) -----------------
__global__ __launch_bounds__(256) void k_colsum() {
    const unsigned* Ah = (const unsigned*)g_aggh4;
    int tid = threadIdx.x;
    int c2 = tid & 127;                // uint index = column pair
    int g = tid >> 7;
    int n0 = blockIdx.x * 200;
    float s0 = 0.f, s1 = 0.f;
    for (int r = g; r < 200; r += 2) {
        unsigned u = Ah[(size_t)(n0 + r) * 128 + c2];
        s0 += __expf(bflo(u));
        s1 += __expf(bfhi(u));
    }
    atomicAdd(&g_colsum[c2 * 2], s0);
    atomicAdd(&g_colsum[c2 * 2 + 1], s1);
}

// ---------------- K8: out = softmaxN(agg) @ Wo^T + b (fused, f32x2) --------
__global__ __launch_bounds__(256) void k_out(const float* __restrict__ Wo,
                                             const float* __restrict__ Wob,
                                             float* __restrict__ out) {
    __shared__ __align__(16) float EsT[32 * 132];   // [c_local][node]
    __shared__ __align__(16) float WoS[32 * 68];    // [c_local][d]
    __shared__ float siv[CC];
    int tid = threadIdx.x;
    int n0 = blockIdx.x * 128;
    int tx = tid & 15, ty = tid >> 4;
    int tx4 = tx * 4, ty4 = ty * 4;
    const unsigned short* Ah = (const unsigned short*)g_aggh4;

    if (tid < CC) siv[tid] = 1.f / g_colsum[tid];
    __syncthreads();

    ull acc2[8][2];
#pragma unroll
    for (int i = 0; i < 8; i++) { acc2[i][0] = 0ull; acc2[i][1] = 0ull; }

    for (int cb = 0; cb < CC; cb += 32) {
#pragma unroll
        for (int r = 0; r < 4; r++) {
            int idx = tid + 256 * r;
            int nd = idx >> 3;                 // 0..127
            int c4 = (idx & 7) << 2;           // 0..28
            int gn = n0 + nd; if (gn >= NN) gn = NN - 1;
            uint2 u = *(const uint2*)&Ah[(size_t)gn * 256 + cb + c4];
            EsT[(c4 + 0) * 132 + nd] = __expf(bflo(u.x)) * siv[cb + c4 + 0];
            EsT[(c4 + 1) * 132 + nd] = __expf(bfhi(u.x)) * siv[cb + c4 + 1];
            EsT[(c4 + 2) * 132 + nd] = __expf(bflo(u.y)) * siv[cb + c4 + 2];
            EsT[(c4 + 3) * 132 + nd] = __expf(bfhi(u.y)) * siv[cb + c4 + 3];
        }
#pragma unroll
        for (int r = 0; r < 2; r++) {
            int idx = tid + 256 * r;
            int d = idx >> 3;                  // 0..63
            int c4 = (idx & 7) << 2;
            float4 w = *(const float4*)&Wo[(size_t)d * CC + cb + c4];
            WoS[(c4 + 0) * 68 + d] = w.x;
            WoS[(c4 + 1) * 68 + d] = w.y;
            WoS[(c4 + 2) * 68 + d] = w.z;
            WoS[(c4 + 3) * 68 + d] = w.w;
        }
        __syncthreads();
#pragma unroll 8
        for (int k = 0; k < 32; k++) {
            float4 a0 = *(const float4*)&EsT[k * 132 + ty4];
            float4 a1 = *(const float4*)&EsT[k * 132 + 64 + ty4];
            ulonglong2 bv = *(const ulonglong2*)&WoS[k * 68 + tx4];
            float av[8] = {a0.x, a0.y, a0.z, a0.w, a1.x, a1.y, a1.z, a1.w};
#pragma unroll
            for (int i = 0; i < 8; i++) {
                ull ad; PACK_DUP(ad, av[i]);
                FMA2(acc2[i][0], ad, bv.x);
                FMA2(acc2[i][1], ad, bv.y);
            }
        }
        __syncthreads();
    }

    float4 bias = *(const float4*)&Wob[tx4];
#pragma unroll
    for (int i = 0; i < 8; i++) {
        int gn = n0 + ((i < 4) ? (ty4 + i) : (64 + ty4 + i - 4));
        if (gn < NN) {
            float v0, v1, v2, v3;
            UNPACK2(v0, v1, acc2[i][0]);
            UNPACK2(v2, v3, acc2[i][1]);
            float4 o = {v0 + bias.x, v1 + bias.y, v2 + bias.z, v3 + bias.w};
            *(float4*)&out[(size_t)gn * 64 + tx4] = o;
        }
    }
}

// ---------------- launch ----------------------------------------------------
extern "C" void kernel_launch(void* const* d_in, const int* in_sizes, int n_in,
                              void* d_out, int out_size) {
    (void)out_size;
    const void* p[8];
    for (int j = 0; j < 8; j++) p[j] = (j < n_in) ? d_in[j] : 0;
    const int want[8] = {2 * EE, NN * DXX, KH * DHH * DXX, KH * DHH,
                         KH * 2 * DHH, KH, DHH * CC, DHH};
    for (int j = 0; j < 8; j++)
        for (int i = 0; i < n_in; i++)
            if (in_sizes[i] == want[j]) { p[j] = d_in[i]; break; }

    const int*   ei  = (const int*)p[0];
    const float* x   = (const float*)p[1];
    const float* Ww  = (const float*)p[2];
    const float* Wb  = (const float*)p[3];
    const float* aw  = (const float*)p[4];
    const float* ab  = (const float*)p[5];
    const float* Wo  = (const float*)p[6];
    const float* Wob = (const float*)p[7];
    float* out = (float*)d_out;

    k_init<<<196, 256>>>();
    dim3 gwx(391, 2);
    k_wx<<<gwx, 256>>>(x, Ww, Wb);
    k_scores<<<(NN + 7) / 8, 256>>>(aw, ab);
    k_hist<<<(EE / 2 + 255) / 256, 256>>>(ei);
    k_scan1<<<SCB, 1024>>>();
    k_scan2<<<1, 64>>>();
    k_scan3<<<SCB, 1024>>>();
    k_scatter<<<(EE / 2 + NN + 255) / 256, 256>>>(ei);
    k_agg<<<(NN + 7) / 8, 256>>>();
    k_colsum<<<250, 256>>>();
    k_out<<<391, 256>>>(Wo, Wob, out);
}

// round 7
// speedup vs baseline: 1.2407x; 1.0693x over previous
#include <cuda_runtime.h>
#include <cuda_bf16.h>
#include <cuda_fp16.h>

typedef unsigned long long ull;

#define NN 50000
#define EE 1600000
#define ETOT 1650000
#define KH 4
#define DHH 64
#define DXX 128
#define CC 256          // KH*DHH
#define NEG 0.01f
#define SCB 49          // scan blocks (49*1024 >= NN)

// ---------------- scratch (static device globals; allocation-free) ----------
__device__ uint2 g_Wxf8[NN * 32];        // 12.8 MB  fp8 Wx[n][c] (256B/row)
__device__ uint4 g_aggh4[NN * 32];       // 25.6 MB  bf16 agg
__device__ float4 g_si4[NN];             // si + ab folded in (per head)
__device__ float4 g_sj4[NN];
__device__ int g_cnt[NN];
__device__ int g_rowptr[NN + 1];
__device__ int g_cur[NN];
__device__ int g_bsum[64];
__device__ int g_csr[ETOT];              // src indices grouped by dst
__device__ float g_colsum[CC];

// ---------------- helpers ---------------------------------------------------
__device__ __forceinline__ float bflo(unsigned u) { return __uint_as_float(u << 16); }
__device__ __forceinline__ float bfhi(unsigned u) { return __uint_as_float(u & 0xffff0000u); }
__device__ __forceinline__ int clampi(int v) {
    return v < 0 ? 0 : (v >= NN ? NN - 1 : v);
}

#define PACK_DUP(d, f) asm("mov.b64 %0, {%1, %1};" : "=l"(d) : "f"(f))
#define FMA2(d, a, b) asm("fma.rn.f32x2 %0, %1, %2, %0;" : "+l"(d) : "l"(a), "l"(b))
#define UNPACK2(lo, hi, d) asm("mov.b64 {%0, %1}, %2;" : "=f"(lo), "=f"(hi) : "l"(d))
// bf16x2: low 16 bits = bf16(lo), high = bf16(hi)
#define PACKBF(r, lo, hi) asm("cvt.rn.bf16x2.f32 %0, %1, %2;" : "=r"(r) : "f"(hi), "f"(lo))
// e4m3x2: low byte = fp8(lo), high byte = fp8(hi)
#define PACKF8(r, lo, hi) \
    asm("cvt.rn.satfinite.e4m3x2.f32 %0, %1, %2;" : "=h"(r) : "f"(hi), "f"(lo))
// fp8 pair -> f16x2 (bit pattern in u32; .x = low byte's value)
#define UNPF8(d, s) asm("cvt.rn.f16x2.e4m3x2 %0, %1;" : "=r"(d) : "h"(s))

__device__ __forceinline__ void f8_to_f16x2(unsigned u32v, __half2& lo, __half2& hi) {
    unsigned short sl = (unsigned short)(u32v & 0xffffu);
    unsigned short sh = (unsigned short)(u32v >> 16);
    unsigned a, b;
    UNPF8(a, sl);
    UNPF8(b, sh);
    lo = *(__half2*)&a;
    hi = *(__half2*)&b;
}

// ---------------- K0: init (cnt=1 accounts for the self loop) ---------------
__global__ void k_init() {
    int i = blockIdx.x * blockDim.x + threadIdx.x;
    if (i < NN) g_cnt[i] = 1;
    if (i < CC) g_colsum[i] = 0.f;
}

// ---------------- K1: Wx = x @ Ww^T + Wb  (fp8 out, f32x2 math) -------------
__global__ __launch_bounds__(256) void k_wx(const float* __restrict__ x,
                                            const float* __restrict__ Ww,
                                            const float* __restrict__ Wb) {
    __shared__ __align__(16) float XsT[32 * 132];   // [k][node]
    __shared__ __align__(16) float WsT[32 * 132];   // [k][col]
    int tid = threadIdx.x;
    int n0 = blockIdx.x * 128;
    int c0 = blockIdx.y * 128;
    int tx = tid & 15, ty = tid >> 4;
    int tx4 = tx * 4, ty4 = ty * 4;

    ull acc2[8][4];
#pragma unroll
    for (int i = 0; i < 8; i++)
#pragma unroll
        for (int j = 0; j < 4; j++) acc2[i][j] = 0ull;

    for (int kc = 0; kc < DXX; kc += 32) {
#pragma unroll
        for (int r = 0; r < 4; r++) {
            int idx = tid + 256 * r;           // 0..1023
            int n = idx >> 3;                  // 0..127
            int k4 = (idx & 7) << 2;           // 0,4,..,28
            int gn = n0 + n; if (gn >= NN) gn = NN - 1;
            float4 v = *(const float4*)&x[(size_t)gn * DXX + kc + k4];
            XsT[(k4 + 0) * 132 + n] = v.x;
            XsT[(k4 + 1) * 132 + n] = v.y;
            XsT[(k4 + 2) * 132 + n] = v.z;
            XsT[(k4 + 3) * 132 + n] = v.w;
            float4 w = *(const float4*)&Ww[(size_t)(c0 + n) * DXX + kc + k4];
            WsT[(k4 + 0) * 132 + n] = w.x;
            WsT[(k4 + 1) * 132 + n] = w.y;
            WsT[(k4 + 2) * 132 + n] = w.z;
            WsT[(k4 + 3) * 132 + n] = w.w;
        }
        __syncthreads();
#pragma unroll 8
        for (int k = 0; k < 32; k++) {
            float4 a0 = *(const float4*)&XsT[k * 132 + ty4];
            float4 a1 = *(const float4*)&XsT[k * 132 + 64 + ty4];
            ulonglong2 bp0 = *(const ulonglong2*)&WsT[k * 132 + tx4];
            ulonglong2 bp1 = *(const ulonglong2*)&WsT[k * 132 + 64 + tx4];
            float av[8] = {a0.x, a0.y, a0.z, a0.w, a1.x, a1.y, a1.z, a1.w};
#pragma unroll
            for (int i = 0; i < 8; i++) {
                ull ad; PACK_DUP(ad, av[i]);
                FMA2(acc2[i][0], ad, bp0.x);
                FMA2(acc2[i][1], ad, bp0.y);
                FMA2(acc2[i][2], ad, bp1.x);
                FMA2(acc2[i][3], ad, bp1.y);
            }
        }
        __syncthreads();
    }

    float b[8];
#pragma unroll
    for (int j = 0; j < 4; j++) { b[j] = Wb[c0 + tx4 + j]; b[4 + j] = Wb[c0 + 64 + tx4 + j]; }
    unsigned* W8 = (unsigned*)g_Wxf8;
#pragma unroll
    for (int i = 0; i < 8; i++) {
        int gn = n0 + ((i < 4) ? (ty4 + i) : (64 + ty4 + i - 4));
        if (gn < NN) {
            float v[8];
#pragma unroll
            for (int j = 0; j < 4; j++) UNPACK2(v[2 * j], v[2 * j + 1], acc2[i][j]);
            unsigned short q01, q23, q45, q67;
            PACKF8(q01, v[0] + b[0], v[1] + b[1]);
            PACKF8(q23, v[2] + b[2], v[3] + b[3]);
            PACKF8(q45, v[4] + b[4], v[5] + b[5]);
            PACKF8(q67, v[6] + b[6], v[7] + b[7]);
            unsigned w0 = (unsigned)q01 | ((unsigned)q23 << 16);
            unsigned w1 = (unsigned)q45 | ((unsigned)q67 << 16);
            W8[(size_t)gn * 64 + ((c0 + tx4) >> 2)] = w0;
            W8[(size_t)gn * 64 + ((c0 + tx4) >> 2) + 16] = w1;
        }
    }
}

// ---------------- K2: si/sj scores from fp8 Wx (8 lanes per head) ----------
__global__ __launch_bounds__(256) void k_scores(const float* __restrict__ aw,
                                                const float* __restrict__ ab) {
    int n = (blockIdx.x << 3) + (threadIdx.x >> 5);
    int lane = threadIdx.x & 31;
    if (n >= NN) return;
    int h = lane >> 3;                 // head
    int dd = (lane & 7) * 8;           // within-head col base
    uint2 u = g_Wxf8[(size_t)n * 32 + lane];
    __half2 h0, h1, h2, h3;
    f8_to_f16x2(u.x, h0, h1);
    f8_to_f16x2(u.y, h2, h3);
    float2 p0 = __half22float2(h0), p1 = __half22float2(h1);
    float2 p2 = __half22float2(h2), p3 = __half22float2(h3);
    float f[8] = {p0.x, p0.y, p1.x, p1.y, p2.x, p2.y, p3.x, p3.y};
    const float* ai = aw + h * 128 + dd;
    const float* aj = ai + 64;
    float va = 0.f, vb = 0.f;
#pragma unroll
    for (int j = 0; j < 8; j++) { va += f[j] * ai[j]; vb += f[j] * aj[j]; }
#pragma unroll
    for (int o = 4; o; o >>= 1) {
        va += __shfl_xor_sync(0xffffffffu, va, o);
        vb += __shfl_xor_sync(0xffffffffu, vb, o);
    }
    if ((lane & 7) == 0) {
        ((float*)g_si4)[n * 4 + h] = va + ab[h];
        ((float*)g_sj4)[n * 4 + h] = vb;
    }
}

// ---------------- K3: degree histogram, 2 edges/thread ----------------------
__global__ void k_hist(const int* __restrict__ ei) {
    int i = blockIdx.x * blockDim.x + threadIdx.x;
    if (i >= EE / 2) return;
    int2 d2 = *(const int2*)&ei[EE + 2 * i];
    atomicAdd(&g_cnt[clampi(d2.x)], 1);
    atomicAdd(&g_cnt[clampi(d2.y)], 1);
}

// ---------------- K4abc: parallel exclusive scan ---------------------------
__global__ __launch_bounds__(1024) void k_scan1() {
    __shared__ int wsum[32];
    int tid = threadIdx.x, lane = tid & 31, wid = tid >> 5;
    int i = blockIdx.x * 1024 + tid;
    int v = (i < NN) ? g_cnt[i] : 0;
    int s = v;
#pragma unroll
    for (int o = 1; o < 32; o <<= 1) {
        int t = __shfl_up_sync(0xffffffffu, s, o);
        if (lane >= o) s += t;
    }
    if (lane == 31) wsum[wid] = s;
    __syncthreads();
    if (wid == 0) {
        int ws = wsum[lane];
#pragma unroll
        for (int o = 1; o < 32; o <<= 1) {
            int t = __shfl_up_sync(0xffffffffu, ws, o);
            if (lane >= o) ws += t;
        }
        wsum[lane] = ws;
    }
    __syncthreads();
    int incl = s + (wid > 0 ? wsum[wid - 1] : 0);
    if (i < NN) { g_rowptr[i + 1] = incl; g_cur[i] = incl - v; }
    if (tid == 1023) g_bsum[blockIdx.x] = incl;
}
__global__ void k_scan2() {       // 64 threads, scan SCB block totals
    int tid = threadIdx.x, lane = tid & 31, wid = tid >> 5;
    __shared__ int w0;
    int v = (tid < SCB) ? g_bsum[tid] : 0;
    int s = v;
#pragma unroll
    for (int o = 1; o < 32; o <<= 1) {
        int t = __shfl_up_sync(0xffffffffu, s, o);
        if (lane >= o) s += t;
    }
    if (tid == 31) w0 = s;
    __syncthreads();
    if (wid == 1) s += w0;
    if (tid < SCB) g_bsum[tid] = s - v;   // exclusive
}
__global__ __launch_bounds__(1024) void k_scan3() {
    int off = g_bsum[blockIdx.x];
    int i = blockIdx.x * 1024 + threadIdx.x;
    if (i < NN) { g_rowptr[i + 1] += off; g_cur[i] += off; }
    if (i == 0) g_rowptr[0] = 0;
}

// ---------------- K5: scatter src into CSR (2 edges/thread + loops) --------
__global__ void k_scatter(const int* __restrict__ ei) {
    int i = blockIdx.x * blockDim.x + threadIdx.x;
    if (i < EE / 2) {
        int2 s2 = *(const int2*)&ei[2 * i];
        int2 d2 = *(const int2*)&ei[EE + 2 * i];
        int pa = atomicAdd(&g_cur[clampi(d2.x)], 1);
        int pb = atomicAdd(&g_cur[clampi(d2.y)], 1);
        if (pa < ETOT) g_csr[pa] = clampi(s2.x);
        if (pb < ETOT) g_csr[pb] = clampi(s2.y);
    } else {
        int n = i - EE / 2;
        if (n < NN) {
            int pos = atomicAdd(&g_cur[n], 1);
            if (pos < ETOT) g_csr[pos] = n;
        }
    }
}

// ---------------- K6: single-pass edge softmax + fp8 gather, depth-4 -------
__global__ __launch_bounds__(256) void k_agg() {
    int n = (blockIdx.x << 3) + (threadIdx.x >> 5);
    int lane = threadIdx.x & 31;
    if (n >= NN) return;
    int h = lane >> 3;
    int s = g_rowptr[n], en = g_rowptr[n + 1];
    float4 siv = g_si4[n];
    float si = (h < 2) ? (h ? siv.y : siv.x) : ((h == 3) ? siv.w : siv.z);

    __half2 acc[4];
#pragma unroll
    for (int q = 0; q < 4; q++) acc[q] = __float2half2_rn(0.f);
    float den = 0.f;

    int srcA = g_csr[s];
    int srcB = (s + 1 < en) ? g_csr[s + 1] : srcA;
    float4 sjA = g_sj4[srcA], sjB = g_sj4[srcB];
    uint2 uA = g_Wxf8[(size_t)srcA * 32 + lane];
    uint2 uB = g_Wxf8[(size_t)srcB * 32 + lane];

    for (int e = s; e < en; e += 2) {
        int nA = (e + 2 < en) ? g_csr[e + 2] : srcA;
        int nB = (e + 3 < en) ? g_csr[e + 3] : srcA;
        float4 sjAn = g_sj4[nA];
        uint2 uAn = g_Wxf8[(size_t)nA * 32 + lane];
        float4 sjBn = g_sj4[nB];
        uint2 uBn = g_Wxf8[(size_t)nB * 32 + lane];

        {
            float sj = (h < 2) ? (h ? sjA.y : sjA.x) : ((h == 3) ? sjA.w : sjA.z);
            float t = si + sj; t = t < 0.f ? NEG * t : t;
            float c = __expf(t);
            den += c;
            __half2 ch = __float2half2_rn(c);
            __half2 w0, w1, w2, w3;
            f8_to_f16x2(uA.x, w0, w1);
            f8_to_f16x2(uA.y, w2, w3);
            acc[0] = __hfma2(ch, w0, acc[0]);
            acc[1] = __hfma2(ch, w1, acc[1]);
            acc[2] = __hfma2(ch, w2, acc[2]);
            acc[3] = __hfma2(ch, w3, acc[3]);
        }
        if (e + 1 < en) {
            float sj = (h < 2) ? (h ? sjB.y : sjB.x) : ((h == 3) ? sjB.w : sjB.z);
            float t = si + sj; t = t < 0.f ? NEG * t : t;
            float c = __expf(t);
            den += c;
            __half2 ch = __float2half2_rn(c);
            __half2 w0, w1, w2, w3;
            f8_to_f16x2(uB.x, w0, w1);
            f8_to_f16x2(uB.y, w2, w3);
            acc[0] = __hfma2(ch, w0, acc[0]);
            acc[1] = __hfma2(ch, w1, acc[1]);
            acc[2] = __hfma2(ch, w2, acc[2]);
            acc[3] = __hfma2(ch, w3, acc[3]);
        }
        sjA = sjAn; uA = uAn; sjB = sjBn; uB = uBn;
    }
    float inv = 1.f / den;
    float2 f0 = __half22float2(acc[0]);
    float2 f1 = __half22float2(acc[1]);
    float2 f2 = __half22float2(acc[2]);
    float2 f3 = __half22float2(acc[3]);
    unsigned p0, p1, p2, p3;
    PACKBF(p0, f0.x * inv, f0.y * inv);
    PACKBF(p1, f1.x * inv, f1.y * inv);
    PACKBF(p2, f2.x * inv, f2.y * inv);
    PACKBF(p3, f3.x * inv, f3.y * inv);
    g_aggh4[(size_t)n * 32 + lane] = make_uint4(p0, p1, p2, p3);
}

// ---------------- K7: column exp-sum (no max-shift needed) -----------------
__global__ __launch_bounds__(256) void k_colsum() {
    const unsigned* Ah = (const unsigned*)g_aggh4;
    int tid = threadIdx.x;
    int c2 = tid & 127;                // uint index = column pair
    int g = tid >> 7;
    int n0 = blockIdx.x * 200;
    float s0 = 0.f, s1 = 0.f;
    for (int r = g; r < 200; r += 2) {
        unsigned u = Ah[(size_t)(n0 + r) * 128 + c2];
        s0 += __expf(bflo(u));
        s1 += __expf(bfhi(u));
    }
    atomicAdd(&g_colsum[c2 * 2], s0);
    atomicAdd(&g_colsum[c2 * 2 + 1], s1);
}

// ---------------- K8: out = softmaxN(agg) @ Wo^T + b (fused, f32x2) --------
__global__ __launch_bounds__(256) void k_out(const float* __restrict__ Wo,
                                             const float* __restrict__ Wob,
                                             float* __restrict__ out) {
    __shared__ __align__(16) float EsT[32 * 132];   // [c_local][node]
    __shared__ __align__(16) float WoS[32 * 68];    // [c_local][d]
    __shared__ float siv[CC];
    int tid = threadIdx.x;
    int n0 = blockIdx.x * 128;
    int tx = tid & 15, ty = tid >> 4;
    int tx4 = tx * 4, ty4 = ty * 4;
    const unsigned short* Ah = (const unsigned short*)g_aggh4;

    if (tid < CC) siv[tid] = 1.f / g_colsum[tid];
    __syncthreads();

    ull acc2[8][2];
#pragma unroll
    for (int i = 0; i < 8; i++) { acc2[i][0] = 0ull; acc2[i][1] = 0ull; }

    for (int cb = 0; cb < CC; cb += 32) {
#pragma unroll
        for (int r = 0; r < 4; r++) {
            int idx = tid + 256 * r;
            int nd = idx >> 3;                 // 0..127
            int c4 = (idx & 7) << 2;           // 0..28
            int gn = n0 + nd; if (gn >= NN) gn = NN - 1;
            uint2 u = *(const uint2*)&Ah[(size_t)gn * 256 + cb + c4];
            EsT[(c4 + 0) * 132 + nd] = __expf(bflo(u.x)) * siv[cb + c4 + 0];
            EsT[(c4 + 1) * 132 + nd] = __expf(bfhi(u.x)) * siv[cb + c4 + 1];
            EsT[(c4 + 2) * 132 + nd] = __expf(bflo(u.y)) * siv[cb + c4 + 2];
            EsT[(c4 + 3) * 132 + nd] = __expf(bfhi(u.y)) * siv[cb + c4 + 3];
        }
#pragma unroll
        for (int r = 0; r < 2; r++) {
            int idx = tid + 256 * r;
            int d = idx >> 3;                  // 0..63
            int c4 = (idx & 7) << 2;
            float4 w = *(const float4*)&Wo[(size_t)d * CC + cb + c4];
            WoS[(c4 + 0) * 68 + d] = w.x;
            WoS[(c4 + 1) * 68 + d] = w.y;
            WoS[(c4 + 2) * 68 + d] = w.z;
            WoS[(c4 + 3) * 68 + d] = w.w;
        }
        __syncthreads();
#pragma unroll 8
        for (int k = 0; k < 32; k++) {
            float4 a0 = *(const float4*)&EsT[k * 132 + ty4];
            float4 a1 = *(const float4*)&EsT[k * 132 + 64 + ty4];
            ulonglong2 bv = *(const ulonglong2*)&WoS[k * 68 + tx4];
            float av[8] = {a0.x, a0.y, a0.z, a0.w, a1.x, a1.y, a1.z, a1.w};
#pragma unroll
            for (int i = 0; i < 8; i++) {
                ull ad; PACK_DUP(ad, av[i]);
                FMA2(acc2[i][0], ad, bv.x);
                FMA2(acc2[i][1], ad, bv.y);
            }
        }
        __syncthreads();
    }

    float4 bias = *(const float4*)&Wob[tx4];
#pragma unroll
    for (int i = 0; i < 8; i++) {
        int gn = n0 + ((i < 4) ? (ty4 + i) : (64 + ty4 + i - 4));
        if (gn < NN) {
            float v0, v1, v2, v3;
            UNPACK2(v0, v1, acc2[i][0]);
            UNPACK2(v2, v3, acc2[i][1]);
            float4 o = {v0 + bias.x, v1 + bias.y, v2 + bias.z, v3 + bias.w};
            *(float4*)&out[(size_t)gn * 64 + tx4] = o;
        }
    }
}

// ---------------- launch ----------------------------------------------------
extern "C" void kernel_launch(void* const* d_in, const int* in_sizes, int n_in,
                              void* d_out, int out_size) {
    (void)out_size;
    const void* p[8];
    for (int j = 0; j < 8; j++) p[j] = (j < n_in) ? d_in[j] : 0;
    const int want[8] = {2 * EE, NN * DXX, KH * DHH * DXX, KH * DHH,
                         KH * 2 * DHH, KH, DHH * CC, DHH};
    for (int j = 0; j < 8; j++)
        for (int i = 0; i < n_in; i++)
            if (in_sizes[i] == want[j]) { p[j] = d_in[i]; break; }

    const int*   ei  = (const int*)p[0];
    const float* x   = (const float*)p[1];
    const float* Ww  = (const float*)p[2];
    const float* Wb  = (const float*)p[3];
    const float* aw  = (const float*)p[4];
    const float* ab  = (const float*)p[5];
    const float* Wo  = (const float*)p[6];
    const float* Wob = (const float*)p[7];
    float* out = (float*)d_out;

    k_init<<<196, 256>>>();
    dim3 gwx(391, 2);
    k_wx<<<gwx, 256>>>(x, Ww, Wb);
    k_scores<<<(NN + 7) / 8, 256>>>(aw, ab);
    k_hist<<<(EE / 2 + 255) / 256, 256>>>(ei);
    k_scan1<<<SCB, 1024>>>();
    k_scan2<<<1, 64>>>();
    k_scan3<<<SCB, 1024>>>();
    k_scatter<<<(EE / 2 + NN + 255) / 256, 256>>>(ei);
    k_agg<<<(NN + 7) / 8, 256>>>();
    k_colsum<<<250, 256>>>();
    k_out<<<391, 256>>>(Wo, Wob, out);
}

// round 8
// speedup vs baseline: 1.7965x; 1.4480x over previous
#include <cuda_runtime.h>
#include <cuda_bf16.h>
#include <cuda_fp16.h>
#include <cstdint>

typedef unsigned long long ull;

#define NN 50000
#define EE 1600000
#define ETOT 1650000
#define KH 4
#define DHH 64
#define DXX 128
#define CC 256          // KH*DHH
#define NEG 0.01f
#define SCB 49          // scan blocks (49*1024 >= NN)

// ---------------- scratch (static device globals; allocation-free) ----------
__device__ uint2 g_Wxf8[NN * 32];        // 12.8 MB  fp8 Wx[n][c] (256B/row)
__device__ uint4 g_aggh4[NN * 32];       // 25.6 MB  bf16 E = exp(agg)
__device__ float4 g_si4[NN];             // si + ab folded in (per head)
__device__ float4 g_sj4[NN];
__device__ int g_cnt[NN];
__device__ int g_rowptr[NN + 1];
__device__ int g_cur[NN];
__device__ int g_bsum[64];
__device__ int g_csr[ETOT];              // src indices grouped by dst
__device__ float g_colsum[CC];

// ---------------- helpers ---------------------------------------------------
__device__ __forceinline__ float bflo(unsigned u) { return __uint_as_float(u << 16); }
__device__ __forceinline__ float bfhi(unsigned u) { return __uint_as_float(u & 0xffff0000u); }
__device__ __forceinline__ int clampi(int v) {
    return v < 0 ? 0 : (v >= NN ? NN - 1 : v);
}

// bf16x2: low 16 bits = bf16(lo), high = bf16(hi)
#define PACKBF(r, lo, hi) asm("cvt.rn.bf16x2.f32 %0, %1, %2;" : "=r"(r) : "f"(hi), "f"(lo))
// e4m3x2: low byte = fp8(lo), high byte = fp8(hi)
#define PACKF8(r, lo, hi) \
    asm("cvt.rn.satfinite.e4m3x2.f32 %0, %1, %2;" : "=h"(r) : "f"(hi), "f"(lo))
// fp8 pair -> f16x2
#define UNPF8(d, s) asm("cvt.rn.f16x2.e4m3x2 %0, %1;" : "=r"(d) : "h"(s))

__device__ __forceinline__ void f8_to_f16x2(unsigned u32v, __half2& lo, __half2& hi) {
    unsigned short sl = (unsigned short)(u32v & 0xffffu);
    unsigned short sh = (unsigned short)(u32v >> 16);
    unsigned a, b;
    UNPF8(a, sl);
    UNPF8(b, sh);
    lo = *(__half2*)&a;
    hi = *(__half2*)&b;
}

#define LDSM4(r0, r1, r2, r3, a) asm volatile( \
    "ldmatrix.sync.aligned.m8n8.x4.shared.b16 {%0,%1,%2,%3}, [%4];" \
    : "=r"(r0), "=r"(r1), "=r"(r2), "=r"(r3) : "r"(a))
#define LDSM2(r0, r1, a) asm volatile( \
    "ldmatrix.sync.aligned.m8n8.x2.shared.b16 {%0,%1}, [%2];" \
    : "=r"(r0), "=r"(r1) : "r"(a))
#define MMA16816(d, a, b) asm volatile( \
    "mma.sync.aligned.m16n8k16.row.col.f32.bf16.bf16.f32 " \
    "{%0,%1,%2,%3}, {%4,%5,%6,%7}, {%8,%9}, {%0,%1,%2,%3};" \
    : "+f"((d)[0]), "+f"((d)[1]), "+f"((d)[2]), "+f"((d)[3]) \
    : "r"((a)[0]), "r"((a)[1]), "r"((a)[2]), "r"((a)[3]), "r"((b)[0]), "r"((b)[1]))

__device__ __forceinline__ unsigned pack_bf2(float lo, float hi) {
    unsigned r; PACKBF(r, lo, hi); return r;
}

// ---------------- K0: init (cnt=1 accounts for the self loop) ---------------
__global__ void k_init() {
    int i = blockIdx.x * blockDim.x + threadIdx.x;
    if (i < NN) g_cnt[i] = 1;
    if (i < CC) g_colsum[i] = 0.f;
}

// ---------------- K1: Wx = x @ Ww^T + Wb  (bf16 mma.sync, fp8 out) ----------
// CTA tile 128(M) x 128(N), K=128 in 2 chunks of 64. 8 warps, 64x32 each.
__global__ __launch_bounds__(256) void k_wx(const float* __restrict__ x,
                                            const float* __restrict__ Ww,
                                            const float* __restrict__ Wb) {
    __shared__ __align__(16) char smbuf[36864];
    __shared__ float biasS[128];
    __nv_bfloat16* As = (__nv_bfloat16*)smbuf;            // [128][72]
    __nv_bfloat16* Bs = (__nv_bfloat16*)(smbuf + 18432);  // [128][72]
    unsigned short* Cs = (unsigned short*)smbuf;          // [128][72] (overlay)
    int tid = threadIdx.x, lane = tid & 31, wid = tid >> 5;
    int n0 = blockIdx.x * 128, c0 = blockIdx.y * 128;
    int wm = wid >> 2, wn = wid & 3;       // warp grid 2x4
    uint32_t asb = (uint32_t)__cvta_generic_to_shared(As);
    uint32_t bsb = (uint32_t)__cvta_generic_to_shared(Bs);

    if (tid < 128) biasS[tid] = Wb[c0 + tid];

    float acc[4][4][4];
#pragma unroll
    for (int mt = 0; mt < 4; mt++)
#pragma unroll
        for (int nt = 0; nt < 4; nt++)
#pragma unroll
            for (int r = 0; r < 4; r++) acc[mt][nt][r] = 0.f;

    for (int kc = 0; kc < DXX; kc += 64) {
        __syncthreads();
        // stage A: x[n0+row][kc + q*4 ..] -> bf16
#pragma unroll
        for (int j = 0; j < 8; j++) {
            int lin = tid + 256 * j;             // 0..2047
            int row = lin >> 4, q = lin & 15;
            int gn = n0 + row; if (gn >= NN) gn = NN - 1;
            float4 v = *(const float4*)&x[(size_t)gn * DXX + kc + q * 4];
            uint2 o = make_uint2(pack_bf2(v.x, v.y), pack_bf2(v.z, v.w));
            *(uint2*)&As[row * 72 + q * 4] = o;
        }
        // stage B: Ww[c0+row][kc + q*4 ..] -> bf16
#pragma unroll
        for (int j = 0; j < 8; j++) {
            int lin = tid + 256 * j;
            int row = lin >> 4, q = lin & 15;
            float4 v = *(const float4*)&Ww[(size_t)(c0 + row) * DXX + kc + q * 4];
            uint2 o = make_uint2(pack_bf2(v.x, v.y), pack_bf2(v.z, v.w));
            *(uint2*)&Bs[row * 72 + q * 4] = o;
        }
        __syncthreads();
#pragma unroll
        for (int ks = 0; ks < 4; ks++) {
            int k0 = ks * 16;
            uint32_t a[4][4], b[4][2];
#pragma unroll
            for (int mt = 0; mt < 4; mt++) {
                uint32_t ad = asb + ((wm * 64 + mt * 16 + (lane & 15)) * 72 +
                                     k0 + (lane >> 4) * 8) * 2;
                LDSM4(a[mt][0], a[mt][1], a[mt][2], a[mt][3], ad);
            }
#pragma unroll
            for (int nt = 0; nt < 4; nt++) {
                uint32_t bd = bsb + ((wn * 32 + nt * 8 + (lane & 7)) * 72 +
                                     k0 + ((lane >> 3) & 1) * 8) * 2;
                LDSM2(b[nt][0], b[nt][1], bd);
            }
#pragma unroll
            for (int mt = 0; mt < 4; mt++)
#pragma unroll
                for (int nt = 0; nt < 4; nt++)
                    MMA16816(acc[mt][nt], a[mt], b[nt]);
        }
    }
    __syncthreads();

    // epilogue: bias + fp8 pack into smem, then coalesced uint4 stores
    int tm = lane >> 2, tp = lane & 3;
#pragma unroll
    for (int mt = 0; mt < 4; mt++)
#pragma unroll
        for (int nt = 0; nt < 4; nt++) {
            int row = wm * 64 + mt * 16 + tm;
            int colp = wn * 16 + nt * 4 + tp;    // pair index 0..63
            int c = colp * 2;
            unsigned short u0, u1;
            PACKF8(u0, acc[mt][nt][0] + biasS[c], acc[mt][nt][1] + biasS[c + 1]);
            PACKF8(u1, acc[mt][nt][2] + biasS[c], acc[mt][nt][3] + biasS[c + 1]);
            Cs[row * 72 + colp] = u0;
            Cs[(row + 8) * 72 + colp] = u1;
        }
    __syncthreads();
#pragma unroll
    for (int j = 0; j < 4; j++) {
        int lin = tid + 256 * j;                // 0..1023
        int row = lin >> 3, q = lin & 7;
        int gn = n0 + row;
        if (gn < NN) {
            uint4 v = *(uint4*)&Cs[row * 72 + q * 8];
            ((uint4*)g_Wxf8)[(size_t)gn * 16 + (c0 >> 4) + q] = v;
        }
    }
}

// ---------------- K2: si/sj scores from fp8 Wx (8 lanes per head) ----------
__global__ __launch_bounds__(256) void k_scores(const float* __restrict__ aw,
                                                const float* __restrict__ ab) {
    int n = (blockIdx.x << 3) + (threadIdx.x >> 5);
    int lane = threadIdx.x & 31;
    if (n >= NN) return;
    int h = lane >> 3;                 // head
    int dd = (lane & 7) * 8;           // within-head col base
    uint2 u = g_Wxf8[(size_t)n * 32 + lane];
    __half2 h0, h1, h2, h3;
    f8_to_f16x2(u.x, h0, h1);
    f8_to_f16x2(u.y, h2, h3);
    float2 p0 = __half22float2(h0), p1 = __half22float2(h1);
    float2 p2 = __half22float2(h2), p3 = __half22float2(h3);
    float f[8] = {p0.x, p0.y, p1.x, p1.y, p2.x, p2.y, p3.x, p3.y};
    const float* ai = aw + h * 128 + dd;
    const float* aj = ai + 64;
    float va = 0.f, vb = 0.f;
#pragma unroll
    for (int j = 0; j < 8; j++) { va += f[j] * ai[j]; vb += f[j] * aj[j]; }
#pragma unroll
    for (int o = 4; o; o >>= 1) {
        va += __shfl_xor_sync(0xffffffffu, va, o);
        vb += __shfl_xor_sync(0xffffffffu, vb, o);
    }
    if ((lane & 7) == 0) {
        ((float*)g_si4)[n * 4 + h] = va + ab[h];
        ((float*)g_sj4)[n * 4 + h] = vb;
    }
}

// ---------------- K3: degree histogram, 2 edges/thread ----------------------
__global__ void k_hist(const int* __restrict__ ei) {
    int i = blockIdx.x * blockDim.x + threadIdx.x;
    if (i >= EE / 2) return;
    int2 d2 = *(const int2*)&ei[EE + 2 * i];
    atomicAdd(&g_cnt[clampi(d2.x)], 1);
    atomicAdd(&g_cnt[clampi(d2.y)], 1);
}

// ---------------- K4abc: parallel exclusive scan ---------------------------
__global__ __launch_bounds__(1024) void k_scan1() {
    __shared__ int wsum[32];
    int tid = threadIdx.x, lane = tid & 31, wid = tid >> 5;
    int i = blockIdx.x * 1024 + tid;
    int v = (i < NN) ? g_cnt[i] : 0;
    int s = v;
#pragma unroll
    for (int o = 1; o < 32; o <<= 1) {
        int t = __shfl_up_sync(0xffffffffu, s, o);
        if (lane >= o) s += t;
    }
    if (lane == 31) wsum[wid] = s;
    __syncthreads();
    if (wid == 0) {
        int ws = wsum[lane];
#pragma unroll
        for (int o = 1; o < 32; o <<= 1) {
            int t = __shfl_up_sync(0xffffffffu, ws, o);
            if (lane >= o) ws += t;
        }
        wsum[lane] = ws;
    }
    __syncthreads();
    int incl = s + (wid > 0 ? wsum[wid - 1] : 0);
    if (i < NN) { g_rowptr[i + 1] = incl; g_cur[i] = incl - v; }
    if (tid == 1023) g_bsum[blockIdx.x] = incl;
}
__global__ void k_scan2() {       // 64 threads, scan SCB block totals
    int tid = threadIdx.x, lane = tid & 31, wid = tid >> 5;
    __shared__ int w0;
    int v = (tid < SCB) ? g_bsum[tid] : 0;
    int s = v;
#pragma unroll
    for (int o = 1; o < 32; o <<= 1) {
        int t = __shfl_up_sync(0xffffffffu, s, o);
        if (lane >= o) s += t;
    }
    if (tid == 31) w0 = s;
    __syncthreads();
    if (wid == 1) s += w0;
    if (tid < SCB) g_bsum[tid] = s - v;   // exclusive
}
__global__ __launch_bounds__(1024) void k_scan3() {
    int off = g_bsum[blockIdx.x];
    int i = blockIdx.x * 1024 + threadIdx.x;
    if (i < NN) { g_rowptr[i + 1] += off; g_cur[i] += off; }
    if (i == 0) g_rowptr[0] = 0;
}

// ---------------- K5: scatter src into CSR (2 edges/thread + loops) --------
__global__ void k_scatter(const int* __restrict__ ei) {
    int i = blockIdx.x * blockDim.x + threadIdx.x;
    if (i < EE / 2) {
        int2 s2 = *(const int2*)&ei[2 * i];
        int2 d2 = *(const int2*)&ei[EE + 2 * i];
        int pa = atomicAdd(&g_cur[clampi(d2.x)], 1);
        int pb = atomicAdd(&g_cur[clampi(d2.y)], 1);
        if (pa < ETOT) g_csr[pa] = clampi(s2.x);
        if (pb < ETOT) g_csr[pb] = clampi(s2.y);
    } else {
        int n = i - EE / 2;
        if (n < NN) {
            int pos = atomicAdd(&g_cur[n], 1);
            if (pos < ETOT) g_csr[pos] = n;
        }
    }
}

// ---------------- K6: edge softmax + fp8 gather; store E=exp(agg) bf16 -----
__global__ __launch_bounds__(256) void k_agg() {
    int n = (blockIdx.x << 3) + (threadIdx.x >> 5);
    int lane = threadIdx.x & 31;
    if (n >= NN) return;
    int h = lane >> 3;
    int s = g_rowptr[n], en = g_rowptr[n + 1];
    float4 siv = g_si4[n];
    float si = (h < 2) ? (h ? siv.y : siv.x) : ((h == 3) ? siv.w : siv.z);

    __half2 acc[4];
#pragma unroll
    for (int q = 0; q < 4; q++) acc[q] = __float2half2_rn(0.f);
    float den = 0.f;

    int srcA = g_csr[s];
    int srcB = (s + 1 < en) ? g_csr[s + 1] : srcA;
    float4 sjA = g_sj4[srcA], sjB = g_sj4[srcB];
    uint2 uA = g_Wxf8[(size_t)srcA * 32 + lane];
    uint2 uB = g_Wxf8[(size_t)srcB * 32 + lane];

    for (int e = s; e < en; e += 2) {
        int nA = (e + 2 < en) ? g_csr[e + 2] : srcA;
        int nB = (e + 3 < en) ? g_csr[e + 3] : srcA;
        float4 sjAn = g_sj4[nA];
        uint2 uAn = g_Wxf8[(size_t)nA * 32 + lane];
        float4 sjBn = g_sj4[nB];
        uint2 uBn = g_Wxf8[(size_t)nB * 32 + lane];

        {
            float sj = (h < 2) ? (h ? sjA.y : sjA.x) : ((h == 3) ? sjA.w : sjA.z);
            float t = si + sj; t = t < 0.f ? NEG * t : t;
            float c = __expf(t);
            den += c;
            __half2 ch = __float2half2_rn(c);
            __half2 w0, w1, w2, w3;
            f8_to_f16x2(uA.x, w0, w1);
            f8_to_f16x2(uA.y, w2, w3);
            acc[0] = __hfma2(ch, w0, acc[0]);
            acc[1] = __hfma2(ch, w1, acc[1]);
            acc[2] = __hfma2(ch, w2, acc[2]);
            acc[3] = __hfma2(ch, w3, acc[3]);
        }
        if (e + 1 < en) {
            float sj = (h < 2) ? (h ? sjB.y : sjB.x) : ((h == 3) ? sjB.w : sjB.z);
            float t = si + sj; t = t < 0.f ? NEG * t : t;
            float c = __expf(t);
            den += c;
            __half2 ch = __float2half2_rn(c);
            __half2 w0, w1, w2, w3;
            f8_to_f16x2(uB.x, w0, w1);
            f8_to_f16x2(uB.y, w2, w3);
            acc[0] = __hfma2(ch, w0, acc[0]);
            acc[1] = __hfma2(ch, w1, acc[1]);
            acc[2] = __hfma2(ch, w2, acc[2]);
            acc[3] = __hfma2(ch, w3, acc[3]);
        }
        sjA = sjAn; uA = uAn; sjB = sjBn; uB = uBn;
    }
    float inv = 1.f / den;
    float2 f0 = __half22float2(acc[0]);
    float2 f1 = __half22float2(acc[1]);
    float2 f2 = __half22float2(acc[2]);
    float2 f3 = __half22float2(acc[3]);
    unsigned p0, p1, p2, p3;
    PACKBF(p0, __expf(f0.x * inv), __expf(f0.y * inv));
    PACKBF(p1, __expf(f1.x * inv), __expf(f1.y * inv));
    PACKBF(p2, __expf(f2.x * inv), __expf(f2.y * inv));
    PACKBF(p3, __expf(f3.x * inv), __expf(f3.y * inv));
    g_aggh4[(size_t)n * 32 + lane] = make_uint4(p0, p1, p2, p3);
}

// ---------------- K7: column sum of E (no exp) -----------------------------
__global__ __launch_bounds__(256) void k_colsum() {
    const unsigned* Ah = (const unsigned*)g_aggh4;
    int tid = threadIdx.x;
    int c2 = tid & 127;                // uint index = column pair
    int g = tid >> 7;
    int n0 = blockIdx.x * 200;
    float s0 = 0.f, s1 = 0.f;
    for (int r = g; r < 200; r += 2) {
        unsigned u = Ah[(size_t)(n0 + r) * 128 + c2];
        s0 += bflo(u);
        s1 += bfhi(u);
    }
    atomicAdd(&g_colsum[c2 * 2], s0);
    atomicAdd(&g_colsum[c2 * 2 + 1], s1);
}

// ---------------- K8: out = (E*siv) @ Wo^T + b  (bf16 mma.sync) ------------
// CTA tile 128(M) x 64(N), K=256 in 4 chunks of 64. 8 warps, 32x32 each.
__global__ __launch_bounds__(256) void k_out(const float* __restrict__ Wo,
                                             const float* __restrict__ Wob,
                                             float* __restrict__ out) {
    __shared__ __align__(16) char smbuf[34816];
    __shared__ float sivS[CC];
    __nv_bfloat16* As = (__nv_bfloat16*)smbuf;            // [128][72]
    __nv_bfloat16* Bs = (__nv_bfloat16*)(smbuf + 18432);  // [64][72]
    float* Csf = (float*)smbuf;                           // [128][68] (overlay)
    int tid = threadIdx.x, lane = tid & 31, wid = tid >> 5;
    int n0 = blockIdx.x * 128;
    int wm = wid & 3, wn = wid >> 2;       // warp grid 4(M) x 2(N)
    uint32_t asb = (uint32_t)__cvta_generic_to_shared(As);
    uint32_t bsb = (uint32_t)__cvta_generic_to_shared(Bs);

    sivS[tid] = 1.f / g_colsum[tid];

    float acc[2][4][4];
#pragma unroll
    for (int mt = 0; mt < 2; mt++)
#pragma unroll
        for (int nt = 0; nt < 4; nt++)
#pragma unroll
            for (int r = 0; r < 4; r++) acc[mt][nt][r] = 0.f;

    for (int cb = 0; cb < CC; cb += 64) {
        __syncthreads();
        // stage A: E[gn][cb..cb+63] * siv -> bf16
#pragma unroll
        for (int j = 0; j < 4; j++) {
            int lin = tid + 256 * j;             // 0..1023
            int row = lin >> 3, q = lin & 7;
            int gn = n0 + row; if (gn >= NN) gn = NN - 1;
            uint4 u = g_aggh4[(size_t)gn * 32 + (cb >> 3) + q];
            unsigned ua[4] = {u.x, u.y, u.z, u.w};
            unsigned ou[4];
#pragma unroll
            for (int i = 0; i < 4; i++) {
                int c = cb + q * 8 + 2 * i;
                ou[i] = pack_bf2(bflo(ua[i]) * sivS[c], bfhi(ua[i]) * sivS[c + 1]);
            }
            *(uint4*)&As[row * 72 + q * 8] = make_uint4(ou[0], ou[1], ou[2], ou[3]);
        }
        // stage B: Wo[row][cb + q*4 ..] -> bf16
#pragma unroll
        for (int j = 0; j < 4; j++) {
            int lin = tid + 256 * j;             // 0..1023
            int row = lin >> 4, q = lin & 15;    // 64 rows x 16 float4
            float4 v = *(const float4*)&Wo[(size_t)row * CC + cb + q * 4];
            uint2 o = make_uint2(pack_bf2(v.x, v.y), pack_bf2(v.z, v.w));
            *(uint2*)&Bs[row * 72 + q * 4] = o;
        }
        __syncthreads();
#pragma unroll
        for (int ks = 0; ks < 4; ks++) {
            int k0 = ks * 16;
            uint32_t a[2][4], b[4][2];
#pragma unroll
            for (int mt = 0; mt < 2; mt++) {
                uint32_t ad = asb + ((wm * 32 + mt * 16 + (lane & 15)) * 72 +
                                     k0 + (lane >> 4) * 8) * 2;
                LDSM4(a[mt][0], a[mt][1], a[mt][2], a[mt][3], ad);
            }
#pragma unroll
            for (int nt = 0; nt < 4; nt++) {
                uint32_t bd = bsb + ((wn * 32 + nt * 8 + (lane & 7)) * 72 +
                                     k0 + ((lane >> 3) & 1) * 8) * 2;
                LDSM2(b[nt][0], b[nt][1], bd);
            }
#pragma unroll
            for (int mt = 0; mt < 2; mt++)
#pragma unroll
                for (int nt = 0; nt < 4; nt++)
                    MMA16816(acc[mt][nt], a[mt], b[nt]);
        }
    }
    __syncthreads();

    int tm = lane >> 2, tp = lane & 3;
#pragma unroll
    for (int mt = 0; mt < 2; mt++)
#pragma unroll
        for (int nt = 0; nt < 4; nt++) {
            int row = wm * 32 + mt * 16 + tm;
            int col = wn * 32 + nt * 8 + 2 * tp;
            Csf[row * 68 + col] = acc[mt][nt][0];
            Csf[row * 68 + col + 1] = acc[mt][nt][1];
            Csf[(row + 8) * 68 + col] = acc[mt][nt][2];
            Csf[(row + 8) * 68 + col + 1] = acc[mt][nt][3];
        }
    __syncthreads();
#pragma unroll
    for (int j = 0; j < 8; j++) {
        int lin = tid + 256 * j;                // 0..2047
        int row = lin >> 4, q = lin & 15;
        int gn = n0 + row;
        if (gn < NN) {
            float4 v = *(float4*)&Csf[row * 68 + q * 4];
            float4 b = *(const float4*)&Wob[q * 4];
            float4 o = {v.x + b.x, v.y + b.y, v.z + b.z, v.w + b.w};
            *(float4*)&out[(size_t)gn * 64 + q * 4] = o;
        }
    }
}

// ---------------- launch ----------------------------------------------------
extern "C" void kernel_launch(void* const* d_in, const int* in_sizes, int n_in,
                              void* d_out, int out_size) {
    (void)out_size;
    const void* p[8];
    for (int j = 0; j < 8; j++) p[j] = (j < n_in) ? d_in[j] : 0;
    const int want[8] = {2 * EE, NN * DXX, KH * DHH * DXX, KH * DHH,
                         KH * 2 * DHH, KH, DHH * CC, DHH};
    for (int j = 0; j < 8; j++)
        for (int i = 0; i < n_in; i++)
            if (in_sizes[i] == want[j]) { p[j] = d_in[i]; break; }

    const int*   ei  = (const int*)p[0];
    const float* x   = (const float*)p[1];
    const float* Ww  = (const float*)p[2];
    const float* Wb  = (const float*)p[3];
    const float* aw  = (const float*)p[4];
    const float* ab  = (const float*)p[5];
    const float* Wo  = (const float*)p[6];
    const float* Wob = (const float*)p[7];
    float* out = (float*)d_out;

    k_init<<<196, 256>>>();
    dim3 gwx(391, 2);
    k_wx<<<gwx, 256>>>(x, Ww, Wb);
    k_scores<<<(NN + 7) / 8, 256>>>(aw, ab);
    k_hist<<<(EE / 2 + 255) / 256, 256>>>(ei);
    k_scan1<<<SCB, 1024>>>();
    k_scan2<<<1, 64>>>();
    k_scan3<<<SCB, 1024>>>();
    k_scatter<<<(EE / 2 + NN + 255) / 256, 256>>>(ei);
    k_agg<<<(NN + 7) / 8, 256>>>();
    k_colsum<<<250, 256>>>();
    k_out<<<391, 256>>>(Wo, Wob, out);
}

// round 9
// speedup vs baseline: 1.9801x; 1.1022x over previous
#include <cuda_runtime.h>
#include <cuda_bf16.h>
#include <cuda_fp16.h>
#include <cstdint>

typedef unsigned long long ull;

#define NN 50000
#define EE 1600000
#define ETOT 1650000
#define KH 4
#define DHH 64
#define DXX 128
#define CC 256          // KH*DHH
#define NEG 0.01f
#define SCB 49          // scan blocks (49*1024 >= NN)
#define LOG2E 1.44269504f

// f1: blocks [0,782) = wx tiles, [782, 782+3125) = hist
#define F1_WX 782
#define F1_HIST 3125
// f2: blocks [0,3321) = scatter, [3321, 3321+6250) = scores
#define F2_SCAT 3321
#define F2_SCORE 6250

// ---------------- scratch (static device globals; zero-init at load) --------
__device__ uint2 g_Wxf8[NN * 32];        // 12.8 MB  fp8 Wx[n][c] (256B/row)
__device__ uint4 g_aggh4[NN * 32];       // 25.6 MB  bf16 E = exp(agg)
__device__ float g_sif[NN * KH];         // (si + ab) * log2e, per head
__device__ float g_sjf[NN * KH];         // sj * log2e, per head
__device__ int g_cnt[NN];                // zero-init; re-zeroed by scan1
__device__ int g_rowptr[NN + 1];
__device__ int g_cur[NN];
__device__ int g_bsum[64];
__device__ int g_csr[ETOT];              // src indices grouped by dst
__device__ float g_colsum[CC];           // zero-init; re-zeroed by scan2

// ---------------- helpers ---------------------------------------------------
__device__ __forceinline__ float bflo(unsigned u) { return __uint_as_float(u << 16); }
__device__ __forceinline__ float bfhi(unsigned u) { return __uint_as_float(u & 0xffff0000u); }
__device__ __forceinline__ int clampi(int v) {
    return v < 0 ? 0 : (v >= NN ? NN - 1 : v);
}

#define PACKBF(r, lo, hi) asm("cvt.rn.bf16x2.f32 %0, %1, %2;" : "=r"(r) : "f"(hi), "f"(lo))
#define PACKF8(r, lo, hi) \
    asm("cvt.rn.satfinite.e4m3x2.f32 %0, %1, %2;" : "=h"(r) : "f"(hi), "f"(lo))
#define UNPF8(d, s) asm("cvt.rn.f16x2.e4m3x2 %0, %1;" : "=r"(d) : "h"(s))

__device__ __forceinline__ void f8_to_f16x2(unsigned u32v, __half2& lo, __half2& hi) {
    unsigned short sl = (unsigned short)(u32v & 0xffffu);
    unsigned short sh = (unsigned short)(u32v >> 16);
    unsigned a, b;
    UNPF8(a, sl);
    UNPF8(b, sh);
    lo = *(__half2*)&a;
    hi = *(__half2*)&b;
}

#define LDSM4(r0, r1, r2, r3, a) asm volatile( \
    "ldmatrix.sync.aligned.m8n8.x4.shared.b16 {%0,%1,%2,%3}, [%4];" \
    : "=r"(r0), "=r"(r1), "=r"(r2), "=r"(r3) : "r"(a))
#define LDSM2(r0, r1, a) asm volatile( \
    "ldmatrix.sync.aligned.m8n8.x2.shared.b16 {%0,%1}, [%2];" \
    : "=r"(r0), "=r"(r1) : "r"(a))
#define MMA16816(d, a, b) asm volatile( \
    "mma.sync.aligned.m16n8k16.row.col.f32.bf16.bf16.f32 " \
    "{%0,%1,%2,%3}, {%4,%5,%6,%7}, {%8,%9}, {%0,%1,%2,%3};" \
    : "+f"((d)[0]), "+f"((d)[1]), "+f"((d)[2]), "+f"((d)[3]) \
    : "r"((a)[0]), "r"((a)[1]), "r"((a)[2]), "r"((a)[3]), "r"((b)[0]), "r"((b)[1]))

__device__ __forceinline__ unsigned pack_bf2(float lo, float hi) {
    unsigned r; PACKBF(r, lo, hi); return r;
}

// ---------------- F1: Wx GEMM (bf16 mma.sync, fp8 out) ∥ degree hist -------
__global__ __launch_bounds__(256) void k_f1(const float* __restrict__ x,
                                            const float* __restrict__ Ww,
                                            const float* __restrict__ Wb,
                                            const int* __restrict__ ei) {
    __shared__ __align__(16) char smbuf[36864];
    __shared__ float biasS[128];
    int tid = threadIdx.x, lane = tid & 31, wid = tid >> 5;

    if (blockIdx.x >= F1_WX) {
        // ---- hist role: 2 edges/thread ----
        int i = (blockIdx.x - F1_WX) * 256 + tid;
        if (i < EE / 2) {
            int2 d2 = *(const int2*)&ei[EE + 2 * i];
            atomicAdd(&g_cnt[clampi(d2.x)], 1);
            atomicAdd(&g_cnt[clampi(d2.y)], 1);
        }
        return;
    }

    // ---- wx role: CTA tile 128(M) x 128(N), K=128 in 2 chunks of 64 ----
    __nv_bfloat16* As = (__nv_bfloat16*)smbuf;            // [128][72]
    __nv_bfloat16* Bs = (__nv_bfloat16*)(smbuf + 18432);  // [128][72]
    unsigned short* Cs = (unsigned short*)smbuf;          // [128][72] overlay
    int n0 = (blockIdx.x >> 1) * 128, c0 = (blockIdx.x & 1) * 128;
    int wm = wid >> 2, wn = wid & 3;       // warp grid 2x4
    uint32_t asb = (uint32_t)__cvta_generic_to_shared(As);
    uint32_t bsb = (uint32_t)__cvta_generic_to_shared(Bs);

    if (tid < 128) biasS[tid] = Wb[c0 + tid];

    float acc[4][4][4];
#pragma unroll
    for (int mt = 0; mt < 4; mt++)
#pragma unroll
        for (int nt = 0; nt < 4; nt++)
#pragma unroll
            for (int r = 0; r < 4; r++) acc[mt][nt][r] = 0.f;

    for (int kc = 0; kc < DXX; kc += 64) {
        __syncthreads();
#pragma unroll
        for (int j = 0; j < 8; j++) {
            int lin = tid + 256 * j;             // 0..2047
            int row = lin >> 4, q = lin & 15;
            int gn = n0 + row; if (gn >= NN) gn = NN - 1;
            float4 v = *(const float4*)&x[(size_t)gn * DXX + kc + q * 4];
            uint2 o = make_uint2(pack_bf2(v.x, v.y), pack_bf2(v.z, v.w));
            *(uint2*)&As[row * 72 + q * 4] = o;
        }
#pragma unroll
        for (int j = 0; j < 8; j++) {
            int lin = tid + 256 * j;
            int row = lin >> 4, q = lin & 15;
            float4 v = *(const float4*)&Ww[(size_t)(c0 + row) * DXX + kc + q * 4];
            uint2 o = make_uint2(pack_bf2(v.x, v.y), pack_bf2(v.z, v.w));
            *(uint2*)&Bs[row * 72 + q * 4] = o;
        }
        __syncthreads();
#pragma unroll
        for (int ks = 0; ks < 4; ks++) {
            int k0 = ks * 16;
            uint32_t a[4][4], b[4][2];
#pragma unroll
            for (int mt = 0; mt < 4; mt++) {
                uint32_t ad = asb + ((wm * 64 + mt * 16 + (lane & 15)) * 72 +
                                     k0 + (lane >> 4) * 8) * 2;
                LDSM4(a[mt][0], a[mt][1], a[mt][2], a[mt][3], ad);
            }
#pragma unroll
            for (int nt = 0; nt < 4; nt++) {
                uint32_t bd = bsb + ((wn * 32 + nt * 8 + (lane & 7)) * 72 +
                                     k0 + ((lane >> 3) & 1) * 8) * 2;
                LDSM2(b[nt][0], b[nt][1], bd);
            }
#pragma unroll
            for (int mt = 0; mt < 4; mt++)
#pragma unroll
                for (int nt = 0; nt < 4; nt++)
                    MMA16816(acc[mt][nt], a[mt], b[nt]);
        }
    }
    __syncthreads();

    int tm = lane >> 2, tp = lane & 3;
#pragma unroll
    for (int mt = 0; mt < 4; mt++)
#pragma unroll
        for (int nt = 0; nt < 4; nt++) {
            int row = wm * 64 + mt * 16 + tm;
            int colp = wn * 16 + nt * 4 + tp;    // pair index 0..63
            int c = colp * 2;
            unsigned short u0, u1;
            PACKF8(u0, acc[mt][nt][0] + biasS[c], acc[mt][nt][1] + biasS[c + 1]);
            PACKF8(u1, acc[mt][nt][2] + biasS[c], acc[mt][nt][3] + biasS[c + 1]);
            Cs[row * 72 + colp] = u0;
            Cs[(row + 8) * 72 + colp] = u1;
        }
    __syncthreads();
#pragma unroll
    for (int j = 0; j < 4; j++) {
        int lin = tid + 256 * j;                // 0..1023
        int row = lin >> 3, q = lin & 7;
        int gn = n0 + row;
        if (gn < NN) {
            uint4 v = *(uint4*)&Cs[row * 72 + q * 8];
            ((uint4*)g_Wxf8)[(size_t)gn * 16 + (c0 >> 4) + q] = v;
        }
    }
}

// ---------------- K4abc: parallel exclusive scan (+1 self-loop folded) -----
__global__ __launch_bounds__(1024) void k_scan1() {
    __shared__ int wsum[32];
    int tid = threadIdx.x, lane = tid & 31, wid = tid >> 5;
    int i = blockIdx.x * 1024 + tid;
    int v = 0;
    if (i < NN) {
        v = g_cnt[i] + 1;        // +1 = self loop slot
        g_cnt[i] = 0;            // reset for next replay
    }
    int s = v;
#pragma unroll
    for (int o = 1; o < 32; o <<= 1) {
        int t = __shfl_up_sync(0xffffffffu, s, o);
        if (lane >= o) s += t;
    }
    if (lane == 31) wsum[wid] = s;
    __syncthreads();
    if (wid == 0) {
        int ws = wsum[lane];
#pragma unroll
        for (int o = 1; o < 32; o <<= 1) {
            int t = __shfl_up_sync(0xffffffffu, ws, o);
            if (lane >= o) ws += t;
        }
        wsum[lane] = ws;
    }
    __syncthreads();
    int incl = s + (wid > 0 ? wsum[wid - 1] : 0);
    if (i < NN) { g_rowptr[i + 1] = incl; g_cur[i] = incl - v; }
    if (tid == 1023) g_bsum[blockIdx.x] = incl;
}
__global__ void k_scan2() {       // 64 threads; also zeroes colsum for this run
    int tid = threadIdx.x, lane = tid & 31, wid = tid >> 5;
    __shared__ int w0;
    for (int c = tid; c < CC; c += 64) g_colsum[c] = 0.f;
    int v = (tid < SCB) ? g_bsum[tid] : 0;
    int s = v;
#pragma unroll
    for (int o = 1; o < 32; o <<= 1) {
        int t = __shfl_up_sync(0xffffffffu, s, o);
        if (lane >= o) s += t;
    }
    if (tid == 31) w0 = s;
    __syncthreads();
    if (wid == 1) s += w0;
    if (tid < SCB) g_bsum[tid] = s - v;   // exclusive
}
__global__ __launch_bounds__(1024) void k_scan3() {
    int off = g_bsum[blockIdx.x];
    int i = blockIdx.x * 1024 + threadIdx.x;
    if (i < NN) { g_rowptr[i + 1] += off; g_cur[i] += off; }
    if (i == 0) g_rowptr[0] = 0;
}

// ---------------- F2: scatter ∥ scores --------------------------------------
__global__ __launch_bounds__(256) void k_f2(const float* __restrict__ aw,
                                            const float* __restrict__ ab,
                                            const int* __restrict__ ei) {
    int tid = threadIdx.x;
    if (blockIdx.x < F2_SCAT) {
        // ---- scatter role: 2 edges/thread + self loops ----
        int i = blockIdx.x * 256 + tid;
        if (i < EE / 2) {
            int2 s2 = *(const int2*)&ei[2 * i];
            int2 d2 = *(const int2*)&ei[EE + 2 * i];
            int pa = atomicAdd(&g_cur[clampi(d2.x)], 1);
            int pb = atomicAdd(&g_cur[clampi(d2.y)], 1);
            if (pa < ETOT) g_csr[pa] = clampi(s2.x);
            if (pb < ETOT) g_csr[pb] = clampi(s2.y);
        } else {
            int n = i - EE / 2;
            if (n < NN) {
                int pos = atomicAdd(&g_cur[n], 1);
                if (pos < ETOT) g_csr[pos] = n;
            }
        }
        return;
    }
    // ---- scores role: 8 lanes per head, scaled by log2e ----
    int n = ((blockIdx.x - F2_SCAT) << 3) + (tid >> 5);
    int lane = tid & 31;
    if (n >= NN) return;
    int h = lane >> 3;
    int dd = (lane & 7) * 8;
    uint2 u = g_Wxf8[(size_t)n * 32 + lane];
    __half2 h0, h1, h2, h3;
    f8_to_f16x2(u.x, h0, h1);
    f8_to_f16x2(u.y, h2, h3);
    float2 p0 = __half22float2(h0), p1 = __half22float2(h1);
    float2 p2 = __half22float2(h2), p3 = __half22float2(h3);
    float f[8] = {p0.x, p0.y, p1.x, p1.y, p2.x, p2.y, p3.x, p3.y};
    const float* ai = aw + h * 128 + dd;
    const float* aj = ai + 64;
    float va = 0.f, vb = 0.f;
#pragma unroll
    for (int j = 0; j < 8; j++) { va += f[j] * ai[j]; vb += f[j] * aj[j]; }
#pragma unroll
    for (int o = 4; o; o >>= 1) {
        va += __shfl_xor_sync(0xffffffffu, va, o);
        vb += __shfl_xor_sync(0xffffffffu, vb, o);
    }
    if ((lane & 7) == 0) {
        g_sif[n * 4 + h] = (va + ab[h]) * LOG2E;
        g_sjf[n * 4 + h] = vb * LOG2E;
    }
}

// ---------------- K6: edge softmax + fp8 gather; store E=exp(agg) bf16 -----
__global__ __launch_bounds__(256) void k_agg() {
    int n = (blockIdx.x << 3) + (threadIdx.x >> 5);
    int lane = threadIdx.x & 31;
    if (n >= NN) return;
    int h = lane >> 3;
    int s = g_rowptr[n], en = g_rowptr[n + 1];
    float si = g_sif[n * 4 + h];

    __half2 acc[4];
#pragma unroll
    for (int q = 0; q < 4; q++) acc[q] = __float2half2_rn(0.f);
    float den = 0.f;

    int srcA = g_csr[s];
    int srcB = (s + 1 < en) ? g_csr[s + 1] : srcA;
    float sjA = g_sjf[srcA * 4 + h], sjB = g_sjf[srcB * 4 + h];
    uint2 uA = g_Wxf8[(size_t)srcA * 32 + lane];
    uint2 uB = g_Wxf8[(size_t)srcB * 32 + lane];

    for (int e = s; e < en; e += 2) {
        int nA = (e + 2 < en) ? g_csr[e + 2] : srcA;
        int nB = (e + 3 < en) ? g_csr[e + 3] : srcA;
        float sjAn = g_sjf[nA * 4 + h];
        uint2 uAn = g_Wxf8[(size_t)nA * 32 + lane];
        float sjBn = g_sjf[nB * 4 + h];
        uint2 uBn = g_Wxf8[(size_t)nB * 32 + lane];

        {
            float t = si + sjA; t = t < 0.f ? NEG * t : t;
            float c = exp2f(t);
            den += c;
            __half2 ch = __float2half2_rn(c);
            __half2 w0, w1, w2, w3;
            f8_to_f16x2(uA.x, w0, w1);
            f8_to_f16x2(uA.y, w2, w3);
            acc[0] = __hfma2(ch, w0, acc[0]);
            acc[1] = __hfma2(ch, w1, acc[1]);
            acc[2] = __hfma2(ch, w2, acc[2]);
            acc[3] = __hfma2(ch, w3, acc[3]);
        }
        if (e + 1 < en) {
            float t = si + sjB; t = t < 0.f ? NEG * t : t;
            float c = exp2f(t);
            den += c;
            __half2 ch = __float2half2_rn(c);
            __half2 w0, w1, w2, w3;
            f8_to_f16x2(uB.x, w0, w1);
            f8_to_f16x2(uB.y, w2, w3);
            acc[0] = __hfma2(ch, w0, acc[0]);
            acc[1] = __hfma2(ch, w1, acc[1]);
            acc[2] = __hfma2(ch, w2, acc[2]);
            acc[3] = __hfma2(ch, w3, acc[3]);
        }
        sjA = sjAn; uA = uAn; sjB = sjBn; uB = uBn;
    }
    float inv = 1.f / den;
    float2 f0 = __half22float2(acc[0]);
    float2 f1 = __half22float2(acc[1]);
    float2 f2 = __half22float2(acc[2]);
    float2 f3 = __half22float2(acc[3]);
    unsigned p0, p1, p2, p3;
    PACKBF(p0, __expf(f0.x * inv), __expf(f0.y * inv));
    PACKBF(p1, __expf(f1.x * inv), __expf(f1.y * inv));
    PACKBF(p2, __expf(f2.x * inv), __expf(f2.y * inv));
    PACKBF(p3, __expf(f3.x * inv), __expf(f3.y * inv));
    g_aggh4[(size_t)n * 32 + lane] = make_uint4(p0, p1, p2, p3);
}

// ---------------- K7: column sum of E (no exp) -----------------------------
__global__ __launch_bounds__(256) void k_colsum() {
    const unsigned* Ah = (const unsigned*)g_aggh4;
    int tid = threadIdx.x;
    int c2 = tid & 127;                // uint index = column pair
    int g = tid >> 7;
    int n0 = blockIdx.x * 200;
    float s0 = 0.f, s1 = 0.f;
    for (int r = g; r < 200; r += 2) {
        unsigned u = Ah[(size_t)(n0 + r) * 128 + c2];
        s0 += bflo(u);
        s1 += bfhi(u);
    }
    atomicAdd(&g_colsum[c2 * 2], s0);
    atomicAdd(&g_colsum[c2 * 2 + 1], s1);
}

// ---------------- K8: out = (E*siv) @ Wo^T + b  (bf16 mma.sync) ------------
__global__ __launch_bounds__(256) void k_out(const float* __restrict__ Wo,
                                             const float* __restrict__ Wob,
                                             float* __restrict__ out) {
    __shared__ __align__(16) char smbuf[34816];
    __shared__ float sivS[CC];
    __nv_bfloat16* As = (__nv_bfloat16*)smbuf;            // [128][72]
    __nv_bfloat16* Bs = (__nv_bfloat16*)(smbuf + 18432);  // [64][72]
    float* Csf = (float*)smbuf;                           // [128][68] overlay
    int tid = threadIdx.x, lane = tid & 31, wid = tid >> 5;
    int n0 = blockIdx.x * 128;
    int wm = wid & 3, wn = wid >> 2;       // warp grid 4(M) x 2(N)
    uint32_t asb = (uint32_t)__cvta_generic_to_shared(As);
    uint32_t bsb = (uint32_t)__cvta_generic_to_shared(Bs);

    sivS[tid] = 1.f / g_colsum[tid];

    float acc[2][4][4];
#pragma unroll
    for (int mt = 0; mt < 2; mt++)
#pragma unroll
        for (int nt = 0; nt < 4; nt++)
#pragma unroll
            for (int r = 0; r < 4; r++) acc[mt][nt][r] = 0.f;

    for (int cb = 0; cb < CC; cb += 64) {
        __syncthreads();
#pragma unroll
        for (int j = 0; j < 4; j++) {
            int lin = tid + 256 * j;             // 0..1023
            int row = lin >> 3, q = lin & 7;
            int gn = n0 + row; if (gn >= NN) gn = NN - 1;
            uint4 u = g_aggh4[(size_t)gn * 32 + (cb >> 3) + q];
            unsigned ua[4] = {u.x, u.y, u.z, u.w};
            unsigned ou[4];
#pragma unroll
            for (int i = 0; i < 4; i++) {
                int c = cb + q * 8 + 2 * i;
                ou[i] = pack_bf2(bflo(ua[i]) * sivS[c], bfhi(ua[i]) * sivS[c + 1]);
            }
            *(uint4*)&As[row * 72 + q * 8] = make_uint4(ou[0], ou[1], ou[2], ou[3]);
        }
#pragma unroll
        for (int j = 0; j < 4; j++) {
            int lin = tid + 256 * j;             // 0..1023
            int row = lin >> 4, q = lin & 15;    // 64 rows x 16 float4
            float4 v = *(const float4*)&Wo[(size_t)row * CC + cb + q * 4];
            uint2 o = make_uint2(pack_bf2(v.x, v.y), pack_bf2(v.z, v.w));
            *(uint2*)&Bs[row * 72 + q * 4] = o;
        }
        __syncthreads();
#pragma unroll
        for (int ks = 0; ks < 4; ks++) {
            int k0 = ks * 16;
            uint32_t a[2][4], b[4][2];
#pragma unroll
            for (int mt = 0; mt < 2; mt++) {
                uint32_t ad = asb + ((wm * 32 + mt * 16 + (lane & 15)) * 72 +
                                     k0 + (lane >> 4) * 8) * 2;
                LDSM4(a[mt][0], a[mt][1], a[mt][2], a[mt][3], ad);
            }
#pragma unroll
            for (int nt = 0; nt < 4; nt++) {
                uint32_t bd = bsb + ((wn * 32 + nt * 8 + (lane & 7)) * 72 +
                                     k0 + ((lane >> 3) & 1) * 8) * 2;
                LDSM2(b[nt][0], b[nt][1], bd);
            }
#pragma unroll
            for (int mt = 0; mt < 2; mt++)
#pragma unroll
                for (int nt = 0; nt < 4; nt++)
                    MMA16816(acc[mt][nt], a[mt], b[nt]);
        }
    }
    __syncthreads();

    int tm = lane >> 2, tp = lane & 3;
#pragma unroll
    for (int mt = 0; mt < 2; mt++)
#pragma unroll
        for (int nt = 0; nt < 4; nt++) {
            int row = wm * 32 + mt * 16 + tm;
            int col = wn * 32 + nt * 8 + 2 * tp;
            Csf[row * 68 + col] = acc[mt][nt][0];
            Csf[row * 68 + col + 1] = acc[mt][nt][1];
            Csf[(row + 8) * 68 + col] = acc[mt][nt][2];
            Csf[(row + 8) * 68 + col + 1] = acc[mt][nt][3];
        }
    __syncthreads();
#pragma unroll
    for (int j = 0; j < 8; j++) {
        int lin = tid + 256 * j;                // 0..2047
        int row = lin >> 4, q = lin & 15;
        int gn = n0 + row;
        if (gn < NN) {
            float4 v = *(float4*)&Csf[row * 68 + q * 4];
            float4 b = *(const float4*)&Wob[q * 4];
            float4 o = {v.x + b.x, v.y + b.y, v.z + b.z, v.w + b.w};
            *(float4*)&out[(size_t)gn * 64 + q * 4] = o;
        }
    }
}

// ---------------- launch ----------------------------------------------------
extern "C" void kernel_launch(void* const* d_in, const int* in_sizes, int n_in,
                              void* d_out, int out_size) {
    (void)out_size;
    const void* p[8];
    for (int j = 0; j < 8; j++) p[j] = (j < n_in) ? d_in[j] : 0;
    const int want[8] = {2 * EE, NN * DXX, KH * DHH * DXX, KH * DHH,
                         KH * 2 * DHH, KH, DHH * CC, DHH};
    for (int j = 0; j < 8; j++)
        for (int i = 0; i < n_in; i++)
            if (in_sizes[i] == want[j]) { p[j] = d_in[i]; break; }

    const int*   ei  = (const int*)p[0];
    const float* x   = (const float*)p[1];
    const float* Ww  = (const float*)p[2];
    const float* Wb  = (const float*)p[3];
    const float* aw  = (const float*)p[4];
    const float* ab  = (const float*)p[5];
    const float* Wo  = (const float*)p[6];
    const float* Wob = (const float*)p[7];
    float* out = (float*)d_out;

    k_f1<<<F1_WX + F1_HIST, 256>>>(x, Ww, Wb, ei);
    k_scan1<<<SCB, 1024>>>();
    k_scan2<<<1, 64>>>();
    k_scan3<<<SCB, 1024>>>();
    k_f2<<<F2_SCAT + F2_SCORE, 256>>>(aw, ab, ei);
    k_agg<<<(NN + 7) / 8, 256>>>();
    k_colsum<<<250, 256>>>();
    k_out<<<391, 256>>>(Wo, Wob, out);
}